// round 1
// baseline (speedup 1.0000x reference)
#include <cuda_runtime.h>

// Problem constants (match reference: N=100000, E=1600000, D 64->64->32)
#define NMAX 100000
#define EMAX 1600000

// Scratch (device globals: no allocation allowed)
__device__ int   g_deg[NMAX];
__device__ float g_dinv[NMAX];
__device__ float g_h1s[NMAX * 64];   // (x@W1) * dinv[row]  (gather source, layer 1)
__device__ float g_agg1[NMAX * 64];  // init = h1s (self loop), then edge scatter
__device__ float g_h2s[NMAX * 32];   // (relu(...)@W2) * dinv[row] (gather source, layer 2)

// ---------------------------------------------------------------------------
// Degree / normalization
// ---------------------------------------------------------------------------
__global__ void k_zero_deg(int n) {
    int i = blockIdx.x * blockDim.x + threadIdx.x;
    if (i < n) g_deg[i] = 0;
}

__global__ void k_count(const int* __restrict__ col, int e) {
    int i = blockIdx.x * blockDim.x + threadIdx.x;
    if (i < e) atomicAdd(&g_deg[col[i]], 1);
}

__global__ void k_dinv(int n) {
    int i = blockIdx.x * blockDim.x + threadIdx.x;
    if (i < n) g_dinv[i] = rsqrtf((float)(g_deg[i] + 1));  // +1 self loop; always > 0
}

// ---------------------------------------------------------------------------
// GEMM1: h1s = (x @ W1) * dinv[row];  also init g_agg1 = h1s (self-loop term)
// Block: 64 rows, 128 threads, each thread 4 rows x 8 cols.
// ---------------------------------------------------------------------------
__global__ void k_gemm1(const float* __restrict__ x, const float* __restrict__ W, int n) {
    __shared__ __align__(16) float xs[64][68];   // pad 68: 16B-aligned rows, banks spread
    __shared__ __align__(16) float ws[64][64];

    int t = threadIdx.x;
    int rowbase = blockIdx.x * 64;

    // Load W (64x64 = 1024 float4)
    const float4* W4 = (const float4*)W;
    float4* ws4 = (float4*)ws;
#pragma unroll
    for (int i = t; i < 1024; i += 128) ws4[i] = W4[i];

    // Load x tile (64 rows x 16 float4)
    const float4* x4 = (const float4*)x;
#pragma unroll
    for (int i = t; i < 1024; i += 128) {
        int r = i >> 4, c4 = i & 15;
        int gr = rowbase + r;
        float4 v = make_float4(0.f, 0.f, 0.f, 0.f);
        if (gr < n) v = x4[gr * 16 + c4];
        *(float4*)&xs[r][c4 * 4] = v;
    }
    __syncthreads();

    int tx = t & 7;        // col group: cols tx*8 .. tx*8+7
    int ty = t >> 3;       // row group: rows ty*4 .. ty*4+3
    float acc[4][8];
#pragma unroll
    for (int a = 0; a < 4; a++)
#pragma unroll
        for (int b = 0; b < 8; b++) acc[a][b] = 0.f;

#pragma unroll 16
    for (int k = 0; k < 64; k++) {
        float4 w0 = *(const float4*)&ws[k][tx * 8];
        float4 w1 = *(const float4*)&ws[k][tx * 8 + 4];
#pragma unroll
        for (int rr = 0; rr < 4; rr++) {
            float xv = xs[ty * 4 + rr][k];
            acc[rr][0] += xv * w0.x; acc[rr][1] += xv * w0.y;
            acc[rr][2] += xv * w0.z; acc[rr][3] += xv * w0.w;
            acc[rr][4] += xv * w1.x; acc[rr][5] += xv * w1.y;
            acc[rr][6] += xv * w1.z; acc[rr][7] += xv * w1.w;
        }
    }

    float4* h = (float4*)g_h1s;
    float4* a = (float4*)g_agg1;
#pragma unroll
    for (int rr = 0; rr < 4; rr++) {
        int gr = rowbase + ty * 4 + rr;
        if (gr >= n) break;
        float s = g_dinv[gr];
        float4 o0 = make_float4(acc[rr][0] * s, acc[rr][1] * s, acc[rr][2] * s, acc[rr][3] * s);
        float4 o1 = make_float4(acc[rr][4] * s, acc[rr][5] * s, acc[rr][6] * s, acc[rr][7] * s);
        h[gr * 16 + tx * 2]     = o0;
        h[gr * 16 + tx * 2 + 1] = o1;
        a[gr * 16 + tx * 2]     = o0;
        a[gr * 16 + tx * 2 + 1] = o1;
    }
}

// ---------------------------------------------------------------------------
// Scatter layer 1: g_agg1[col] += g_h1s[row]   (pure, dinv[col] folded into GEMM2 load)
// One thread per (edge, float4-chunk): 16 chunks of 16B per edge.
// ---------------------------------------------------------------------------
__global__ void k_scatter1(const int* __restrict__ row, const int* __restrict__ col, int e) {
    int i = blockIdx.x * blockDim.x + threadIdx.x;
    int idx = i >> 4;
    if (idx >= e) return;
    int c = i & 15;
    int r = row[idx], cl = col[idx];
    float4 v = ((const float4*)g_h1s)[r * 16 + c];
    float* dst = g_agg1 + cl * 64 + c * 4;
    asm volatile("red.global.add.v4.f32 [%0], {%1, %2, %3, %4};"
                 :: "l"(dst), "f"(v.x), "f"(v.y), "f"(v.z), "f"(v.w)
                 : "memory");
}

// ---------------------------------------------------------------------------
// GEMM2: a = relu(agg1*dinv + b1);  h2s = (a @ W2) * dinv;  also init out = h2s
// Block: 64 rows, 128 threads, each thread 4 rows x 4 cols (N=32).
// ---------------------------------------------------------------------------
__global__ void k_gemm2(const float* __restrict__ W2, const float* __restrict__ b1,
                        float* __restrict__ out, int n) {
    __shared__ __align__(16) float xs[64][68];
    __shared__ __align__(16) float ws[64][32];

    int t = threadIdx.x;
    int rowbase = blockIdx.x * 64;

    // Load W2 (64x32 = 512 float4)
    const float4* W4 = (const float4*)W2;
    float4* ws4 = (float4*)ws;
#pragma unroll
    for (int i = t; i < 512; i += 128) ws4[i] = W4[i];

    // Load transformed input tile: relu(agg1 * dinv + b1)
    const float4* a4 = (const float4*)g_agg1;
    const float4* b14 = (const float4*)b1;
#pragma unroll
    for (int i = t; i < 1024; i += 128) {
        int r = i >> 4, c4 = i & 15;
        int gr = rowbase + r;
        float4 v = make_float4(0.f, 0.f, 0.f, 0.f);
        if (gr < n) {
            float4 u = a4[gr * 16 + c4];
            float s = g_dinv[gr];
            float4 bb = b14[c4];
            v.x = fmaxf(fmaf(u.x, s, bb.x), 0.f);
            v.y = fmaxf(fmaf(u.y, s, bb.y), 0.f);
            v.z = fmaxf(fmaf(u.z, s, bb.z), 0.f);
            v.w = fmaxf(fmaf(u.w, s, bb.w), 0.f);
        }
        *(float4*)&xs[r][c4 * 4] = v;
    }
    __syncthreads();

    int tx = t & 7;        // col group: cols tx*4 .. tx*4+3
    int ty = t >> 3;       // row group: rows ty*4 .. ty*4+3
    float acc[4][4];
#pragma unroll
    for (int a = 0; a < 4; a++)
#pragma unroll
        for (int b = 0; b < 4; b++) acc[a][b] = 0.f;

#pragma unroll 16
    for (int k = 0; k < 64; k++) {
        float4 w0 = *(const float4*)&ws[k][tx * 4];
#pragma unroll
        for (int rr = 0; rr < 4; rr++) {
            float xv = xs[ty * 4 + rr][k];
            acc[rr][0] += xv * w0.x; acc[rr][1] += xv * w0.y;
            acc[rr][2] += xv * w0.z; acc[rr][3] += xv * w0.w;
        }
    }

    float4* h = (float4*)g_h2s;
    float4* o4 = (float4*)out;
#pragma unroll
    for (int rr = 0; rr < 4; rr++) {
        int gr = rowbase + ty * 4 + rr;
        if (gr >= n) break;
        float s = g_dinv[gr];
        float4 o = make_float4(acc[rr][0] * s, acc[rr][1] * s, acc[rr][2] * s, acc[rr][3] * s);
        h[gr * 8 + tx]  = o;
        o4[gr * 8 + tx] = o;
    }
}

// ---------------------------------------------------------------------------
// Scatter layer 2: out[col] += g_h2s[row]   (8 chunks of 16B per edge)
// ---------------------------------------------------------------------------
__global__ void k_scatter2(const int* __restrict__ row, const int* __restrict__ col,
                           float* __restrict__ out, int e) {
    int i = blockIdx.x * blockDim.x + threadIdx.x;
    int idx = i >> 3;
    if (idx >= e) return;
    int c = i & 7;
    int r = row[idx], cl = col[idx];
    float4 v = ((const float4*)g_h2s)[r * 8 + c];
    float* dst = out + cl * 32 + c * 4;
    asm volatile("red.global.add.v4.f32 [%0], {%1, %2, %3, %4};"
                 :: "l"(dst), "f"(v.x), "f"(v.y), "f"(v.z), "f"(v.w)
                 : "memory");
}

// ---------------------------------------------------------------------------
// Final: z = out*dinv + b2; out = log_softmax(z). One warp per row (32 cols).
// ---------------------------------------------------------------------------
__global__ void k_lsm(const float* __restrict__ b2, float* __restrict__ out, int n) {
    int gtid = blockIdx.x * blockDim.x + threadIdx.x;
    int rowi = gtid >> 5;
    int lane = gtid & 31;
    if (rowi >= n) return;
    float z = fmaf(out[rowi * 32 + lane], g_dinv[rowi], b2[lane]);
    float m = z;
#pragma unroll
    for (int o = 16; o; o >>= 1) m = fmaxf(m, __shfl_xor_sync(0xFFFFFFFFu, m, o));
    float ex = expf(z - m);
    float s = ex;
#pragma unroll
    for (int o = 16; o; o >>= 1) s += __shfl_xor_sync(0xFFFFFFFFu, s, o);
    out[rowi * 32 + lane] = z - m - logf(s);
}

// ---------------------------------------------------------------------------
extern "C" void kernel_launch(void* const* d_in, const int* in_sizes, int n_in,
                              void* d_out, int out_size) {
    const float* x  = (const float*)d_in[0];
    const int*   ei = (const int*)d_in[1];
    const float* W1 = (const float*)d_in[2];
    const float* b1 = (const float*)d_in[3];
    const float* W2 = (const float*)d_in[4];
    const float* b2 = (const float*)d_in[5];
    float* out = (float*)d_out;

    int n = in_sizes[0] / 64;   // 100000
    int e = in_sizes[1] / 2;    // 1600000
    const int* row = ei;        // sources
    const int* col = ei + e;    // targets

    k_zero_deg<<<(n + 255) / 256, 256>>>(n);
    k_count<<<(e + 255) / 256, 256>>>(col, e);
    k_dinv<<<(n + 255) / 256, 256>>>(n);

    k_gemm1<<<(n + 63) / 64, 128>>>(x, W1, n);

    int w1 = e * 16;  // 25.6M threads
    k_scatter1<<<(w1 + 255) / 256, 256>>>(row, col, e);

    k_gemm2<<<(n + 63) / 64, 128>>>(W2, b1, out, n);

    int w2 = e * 8;   // 12.8M threads
    k_scatter2<<<(w2 + 255) / 256, 256>>>(row, col, out, e);

    k_lsm<<<(n * 32 + 255) / 256, 256>>>(b2, out, n);
}

// round 2
// speedup vs baseline: 1.2117x; 1.2117x over previous
#include <cuda_runtime.h>

// Problem constants (reference: N=100000, E=1600000, D 64->64->32)
#define NMAX 100000
#define EMAX 1600000
#define SCAN_CHUNK 512

// Scratch (device globals: no allocation allowed)
__device__ int   g_deg[NMAX];        // incoming degree (no self loop)
__device__ float g_dinv[NMAX];
__device__ int   g_rowstart[NMAX];   // CSR start per target node
__device__ int   g_cursor[NMAX];     // fill cursors (consumed per launch)
__device__ int   g_src[EMAX];        // CSR: source node per incoming edge
__device__ int   g_bsum[256];
__device__ int   g_boff[256];
__device__ float g_h1s[NMAX * 64];   // (x@W1) * dinv[row]
__device__ float g_agg1[NMAX * 64];  // self + gathered sum
__device__ float g_h2s[NMAX * 32];   // (relu(...)@W2) * dinv[row]

// ---------------------------------------------------------------------------
// Degree / normalization
// ---------------------------------------------------------------------------
__global__ void k_zero_deg(int n) {
    int i = blockIdx.x * blockDim.x + threadIdx.x;
    if (i < n) g_deg[i] = 0;
}

__global__ void k_count(const int* __restrict__ col, int e) {
    int i = blockIdx.x * blockDim.x + threadIdx.x;
    if (i < e) atomicAdd(&g_deg[col[i]], 1);
}

__global__ void k_dinv(int n) {
    int i = blockIdx.x * blockDim.x + threadIdx.x;
    if (i < n) g_dinv[i] = rsqrtf((float)(g_deg[i] + 1));  // +1 self loop
}

// ---------------------------------------------------------------------------
// CSR build: 3-kernel prefix scan over deg, then bucketed fill of src ids.
// ---------------------------------------------------------------------------
// Pass 1: per-block (512 elems) local exclusive scan -> g_rowstart (local), block sum -> g_bsum
__global__ void k_scan1(int n) {
    __shared__ int s_warp[8];
    int t = threadIdx.x;             // 256 threads
    int base = blockIdx.x * SCAN_CHUNK;
    int i0 = base + 2 * t;
    int a = (i0 < n) ? g_deg[i0] : 0;
    int c = (i0 + 1 < n) ? g_deg[i0 + 1] : 0;
    int sum2 = a + c;
    int lane = t & 31, wid = t >> 5;
    int v = sum2;
#pragma unroll
    for (int o = 1; o < 32; o <<= 1) {
        int u = __shfl_up_sync(0xFFFFFFFFu, v, o);
        if (lane >= o) v += u;
    }
    if (lane == 31) s_warp[wid] = v;
    __syncthreads();
    if (t < 8) {
        int w = s_warp[t];
#pragma unroll
        for (int o = 1; o < 8; o <<= 1) {
            int u = __shfl_up_sync(0xFFu, w, o);
            if (t >= o) w += u;
        }
        s_warp[t] = w;
    }
    __syncthreads();
    int woff = wid ? s_warp[wid - 1] : 0;
    int incl = v + woff;
    int excl = incl - sum2;
    if (i0 < n)     g_rowstart[i0] = excl;
    if (i0 + 1 < n) g_rowstart[i0 + 1] = excl + a;
    if (t == 255) g_bsum[blockIdx.x] = incl;
}

// Pass 2: single block exclusive-scans block sums (nb <= 256)
__global__ void k_scan2(int nb) {
    __shared__ int s_warp[8];
    int t = threadIdx.x;
    int v0 = (t < nb) ? g_bsum[t] : 0;
    int lane = t & 31, wid = t >> 5;
    int v = v0;
#pragma unroll
    for (int o = 1; o < 32; o <<= 1) {
        int u = __shfl_up_sync(0xFFFFFFFFu, v, o);
        if (lane >= o) v += u;
    }
    if (lane == 31) s_warp[wid] = v;
    __syncthreads();
    if (t < 8) {
        int w = s_warp[t];
#pragma unroll
        for (int o = 1; o < 8; o <<= 1) {
            int u = __shfl_up_sync(0xFFu, w, o);
            if (t >= o) w += u;
        }
        s_warp[t] = w;
    }
    __syncthreads();
    int woff = wid ? s_warp[wid - 1] : 0;
    if (t < nb) g_boff[t] = v + woff - v0;   // exclusive
}

// Pass 3: add block offsets; init cursors
__global__ void k_scan3(int n) {
    int i = blockIdx.x * blockDim.x + threadIdx.x;
    if (i < n) {
        int v = g_rowstart[i] + g_boff[i / SCAN_CHUNK];
        g_rowstart[i] = v;
        g_cursor[i] = v;
    }
}

// Fill CSR buckets with source ids
__global__ void k_fill(const int* __restrict__ row, const int* __restrict__ col, int e) {
    int i = blockIdx.x * blockDim.x + threadIdx.x;
    if (i < e) {
        int pos = atomicAdd(&g_cursor[col[i]], 1);
        g_src[pos] = row[i];
    }
}

// ---------------------------------------------------------------------------
// GEMM1: h1s = (x @ W1) * dinv[row]
// Block: 64 rows, 128 threads, thread = 4 rows x 8 cols. x read via LDS.128.
// ---------------------------------------------------------------------------
__global__ void k_gemm1(const float* __restrict__ x, const float* __restrict__ W, int n) {
    __shared__ __align__(16) float xs[64][68];
    __shared__ __align__(16) float ws[64][64];

    int t = threadIdx.x;
    int rowbase = blockIdx.x * 64;

    const float4* W4 = (const float4*)W;
    float4* ws4 = (float4*)ws;
#pragma unroll
    for (int i = t; i < 1024; i += 128) ws4[i] = W4[i];

    const float4* x4 = (const float4*)x;
#pragma unroll
    for (int i = t; i < 1024; i += 128) {
        int r = i >> 4, c4 = i & 15;
        int gr = rowbase + r;
        float4 v = make_float4(0.f, 0.f, 0.f, 0.f);
        if (gr < n) v = x4[gr * 16 + c4];
        *(float4*)&xs[r][c4 * 4] = v;
    }
    __syncthreads();

    int tx = t & 7;
    int ty = t >> 3;
    float acc[4][8];
#pragma unroll
    for (int a = 0; a < 4; a++)
#pragma unroll
        for (int b = 0; b < 8; b++) acc[a][b] = 0.f;

#pragma unroll
    for (int k4 = 0; k4 < 64; k4 += 4) {
        float4 xv[4];
#pragma unroll
        for (int rr = 0; rr < 4; rr++) xv[rr] = *(const float4*)&xs[ty * 4 + rr][k4];
#pragma unroll
        for (int kk = 0; kk < 4; kk++) {
            float4 w0 = *(const float4*)&ws[k4 + kk][tx * 8];
            float4 w1 = *(const float4*)&ws[k4 + kk][tx * 8 + 4];
#pragma unroll
            for (int rr = 0; rr < 4; rr++) {
                float xvv = (kk == 0) ? xv[rr].x : (kk == 1) ? xv[rr].y : (kk == 2) ? xv[rr].z : xv[rr].w;
                acc[rr][0] += xvv * w0.x; acc[rr][1] += xvv * w0.y;
                acc[rr][2] += xvv * w0.z; acc[rr][3] += xvv * w0.w;
                acc[rr][4] += xvv * w1.x; acc[rr][5] += xvv * w1.y;
                acc[rr][6] += xvv * w1.z; acc[rr][7] += xvv * w1.w;
            }
        }
    }

    float4* h = (float4*)g_h1s;
#pragma unroll
    for (int rr = 0; rr < 4; rr++) {
        int gr = rowbase + ty * 4 + rr;
        if (gr >= n) break;
        float s = g_dinv[gr];
        h[gr * 16 + tx * 2]     = make_float4(acc[rr][0] * s, acc[rr][1] * s, acc[rr][2] * s, acc[rr][3] * s);
        h[gr * 16 + tx * 2 + 1] = make_float4(acc[rr][4] * s, acc[rr][5] * s, acc[rr][6] * s, acc[rr][7] * s);
    }
}

// ---------------------------------------------------------------------------
// Aggregation layer 1 (CSR gather): agg1[v] = h1s[v] + sum_{u->v} h1s[u]
// One warp per node; lane holds 2 columns (float2). MLP=4 unroll.
// ---------------------------------------------------------------------------
__global__ void k_agg1(int n) {
    int gw = (blockIdx.x * blockDim.x + threadIdx.x) >> 5;
    int lane = threadIdx.x & 31;
    if (gw >= n) return;

    const float2* h = (const float2*)g_h1s;
    float2 acc = h[gw * 32 + lane];            // self loop

    int start = g_rowstart[gw];
    int deg = g_deg[gw];

    for (int j0 = 0; j0 < deg; j0 += 32) {
        int cnt = min(32, deg - j0);
        int src = (lane < cnt) ? g_src[start + j0 + lane] : 0;
        int jj = 0;
        for (; jj + 4 <= cnt; jj += 4) {
            int s0 = __shfl_sync(0xFFFFFFFFu, src, jj);
            int s1 = __shfl_sync(0xFFFFFFFFu, src, jj + 1);
            int s2 = __shfl_sync(0xFFFFFFFFu, src, jj + 2);
            int s3 = __shfl_sync(0xFFFFFFFFu, src, jj + 3);
            float2 v0 = h[s0 * 32 + lane];
            float2 v1 = h[s1 * 32 + lane];
            float2 v2 = h[s2 * 32 + lane];
            float2 v3 = h[s3 * 32 + lane];
            acc.x += v0.x; acc.y += v0.y;
            acc.x += v1.x; acc.y += v1.y;
            acc.x += v2.x; acc.y += v2.y;
            acc.x += v3.x; acc.y += v3.y;
        }
        for (; jj < cnt; jj++) {
            int s = __shfl_sync(0xFFFFFFFFu, src, jj);
            float2 v = h[s * 32 + lane];
            acc.x += v.x; acc.y += v.y;
        }
    }
    ((float2*)g_agg1)[gw * 32 + lane] = acc;
}

// ---------------------------------------------------------------------------
// GEMM2: a = relu(agg1*dinv + b1);  h2s = (a @ W2) * dinv
// Block: 64 rows, 128 threads, thread = 4 rows x 4 cols.
// ---------------------------------------------------------------------------
__global__ void k_gemm2(const float* __restrict__ W2, const float* __restrict__ b1, int n) {
    __shared__ __align__(16) float xs[64][68];
    __shared__ __align__(16) float ws[64][32];

    int t = threadIdx.x;
    int rowbase = blockIdx.x * 64;

    const float4* W4 = (const float4*)W2;
    float4* ws4 = (float4*)ws;
#pragma unroll
    for (int i = t; i < 512; i += 128) ws4[i] = W4[i];

    const float4* a4 = (const float4*)g_agg1;
    const float4* b14 = (const float4*)b1;
#pragma unroll
    for (int i = t; i < 1024; i += 128) {
        int r = i >> 4, c4 = i & 15;
        int gr = rowbase + r;
        float4 v = make_float4(0.f, 0.f, 0.f, 0.f);
        if (gr < n) {
            float4 u = a4[gr * 16 + c4];
            float s = g_dinv[gr];
            float4 bb = b14[c4];
            v.x = fmaxf(fmaf(u.x, s, bb.x), 0.f);
            v.y = fmaxf(fmaf(u.y, s, bb.y), 0.f);
            v.z = fmaxf(fmaf(u.z, s, bb.z), 0.f);
            v.w = fmaxf(fmaf(u.w, s, bb.w), 0.f);
        }
        *(float4*)&xs[r][c4 * 4] = v;
    }
    __syncthreads();

    int tx = t & 7;
    int ty = t >> 3;
    float acc[4][4];
#pragma unroll
    for (int a = 0; a < 4; a++)
#pragma unroll
        for (int b = 0; b < 4; b++) acc[a][b] = 0.f;

#pragma unroll
    for (int k4 = 0; k4 < 64; k4 += 4) {
        float4 xv[4];
#pragma unroll
        for (int rr = 0; rr < 4; rr++) xv[rr] = *(const float4*)&xs[ty * 4 + rr][k4];
#pragma unroll
        for (int kk = 0; kk < 4; kk++) {
            float4 w0 = *(const float4*)&ws[k4 + kk][tx * 4];
#pragma unroll
            for (int rr = 0; rr < 4; rr++) {
                float xvv = (kk == 0) ? xv[rr].x : (kk == 1) ? xv[rr].y : (kk == 2) ? xv[rr].z : xv[rr].w;
                acc[rr][0] += xvv * w0.x; acc[rr][1] += xvv * w0.y;
                acc[rr][2] += xvv * w0.z; acc[rr][3] += xvv * w0.w;
            }
        }
    }

    float4* h = (float4*)g_h2s;
#pragma unroll
    for (int rr = 0; rr < 4; rr++) {
        int gr = rowbase + ty * 4 + rr;
        if (gr >= n) break;
        float s = g_dinv[gr];
        h[gr * 8 + tx] = make_float4(acc[rr][0] * s, acc[rr][1] * s, acc[rr][2] * s, acc[rr][3] * s);
    }
}

// ---------------------------------------------------------------------------
// Aggregation layer 2 + log_softmax fused.
// One warp per node, lane = column (32 cols). MLP=4 unroll.
// ---------------------------------------------------------------------------
__global__ void k_agg2_lsm(const float* __restrict__ b2, float* __restrict__ out, int n) {
    int gw = (blockIdx.x * blockDim.x + threadIdx.x) >> 5;
    int lane = threadIdx.x & 31;
    if (gw >= n) return;

    const float* h = g_h2s;
    float acc = h[gw * 32 + lane];             // self loop

    int start = g_rowstart[gw];
    int deg = g_deg[gw];

    for (int j0 = 0; j0 < deg; j0 += 32) {
        int cnt = min(32, deg - j0);
        int src = (lane < cnt) ? g_src[start + j0 + lane] : 0;
        int jj = 0;
        for (; jj + 4 <= cnt; jj += 4) {
            int s0 = __shfl_sync(0xFFFFFFFFu, src, jj);
            int s1 = __shfl_sync(0xFFFFFFFFu, src, jj + 1);
            int s2 = __shfl_sync(0xFFFFFFFFu, src, jj + 2);
            int s3 = __shfl_sync(0xFFFFFFFFu, src, jj + 3);
            acc += h[s0 * 32 + lane];
            acc += h[s1 * 32 + lane];
            acc += h[s2 * 32 + lane];
            acc += h[s3 * 32 + lane];
        }
        for (; jj < cnt; jj++) {
            int s = __shfl_sync(0xFFFFFFFFu, src, jj);
            acc += h[s * 32 + lane];
        }
    }

    float z = fmaf(acc, g_dinv[gw], b2[lane]);
    float m = z;
#pragma unroll
    for (int o = 16; o; o >>= 1) m = fmaxf(m, __shfl_xor_sync(0xFFFFFFFFu, m, o));
    float ex = expf(z - m);
    float s = ex;
#pragma unroll
    for (int o = 16; o; o >>= 1) s += __shfl_xor_sync(0xFFFFFFFFu, s, o);
    out[gw * 32 + lane] = z - m - logf(s);
}

// ---------------------------------------------------------------------------
extern "C" void kernel_launch(void* const* d_in, const int* in_sizes, int n_in,
                              void* d_out, int out_size) {
    const float* x  = (const float*)d_in[0];
    const int*   ei = (const int*)d_in[1];
    const float* W1 = (const float*)d_in[2];
    const float* b1 = (const float*)d_in[3];
    const float* W2 = (const float*)d_in[4];
    const float* b2 = (const float*)d_in[5];
    float* out = (float*)d_out;

    int n = in_sizes[0] / 64;   // 100000
    int e = in_sizes[1] / 2;    // 1600000
    const int* row = ei;        // sources
    const int* col = ei + e;    // targets

    int nb = (n + SCAN_CHUNK - 1) / SCAN_CHUNK;   // 196

    // degrees + norm
    k_zero_deg<<<(n + 255) / 256, 256>>>(n);
    k_count<<<(e + 255) / 256, 256>>>(col, e);
    k_dinv<<<(n + 255) / 256, 256>>>(n);

    // CSR build
    k_scan1<<<nb, 256>>>(n);
    k_scan2<<<1, 256>>>(nb);
    k_scan3<<<(n + 255) / 256, 256>>>(n);
    k_fill<<<(e + 255) / 256, 256>>>(row, col, e);

    // layer 1
    k_gemm1<<<(n + 63) / 64, 128>>>(x, W1, n);
    k_agg1<<<(n + 7) / 8, 256>>>(n);

    // layer 2 + fused log_softmax
    k_gemm2<<<(n + 63) / 64, 128>>>(W2, b1, n);
    k_agg2_lsm<<<(n + 7) / 8, 256>>>(b2, out, n);
}

// round 4
// speedup vs baseline: 1.4118x; 1.1651x over previous
#include <cuda_runtime.h>
#include <cuda_fp16.h>

// Problem constants (reference: N=100000, E=1600000, D 64->64->32)
#define NMAX 100000
#define EMAX 1600000
#define SCAN_CHUNK 512

// Scratch (device globals: no allocation allowed)
__device__ int    g_deg[NMAX];        // incoming degree (no self loop)
__device__ float  g_dinv[NMAX];
__device__ int    g_rowstart[NMAX];   // CSR start per target node
__device__ int    g_cursor[NMAX];     // fill cursors (consumed per launch)
__device__ int    g_src[EMAX];        // CSR: source node per incoming edge
__device__ int    g_bsum[256];
__device__ int    g_boff[256];
__device__ __half g_h1s[NMAX * 64];   // (x@W1) * dinv[row], fp16 gather source
__device__ float  g_agg1[NMAX * 64];  // self + gathered sum (fp32)
__device__ float  g_h2s[NMAX * 32];   // (relu(...)@W2) * dinv[row] (fp32)

// gemm1 dynamic smem: xs[64][132] + ws[64][64]
#define GEMM1_SMEM_BYTES (64 * 132 * 4 + 64 * 64 * 4)

// ---------------------------------------------------------------------------
// Degree / normalization
// ---------------------------------------------------------------------------
__global__ void k_zero_deg(int n) {
    int i = blockIdx.x * blockDim.x + threadIdx.x;
    if (i < n) g_deg[i] = 0;
}

__global__ void k_count(const int* __restrict__ col, int e) {
    int i = blockIdx.x * blockDim.x + threadIdx.x;
    if (i < e) atomicAdd(&g_deg[col[i]], 1);
}

// ---------------------------------------------------------------------------
// CSR build: prefix scan over deg (dinv fused into pass 1), bucketed fill.
// ---------------------------------------------------------------------------
__global__ void k_scan1(int n) {
    __shared__ int s_warp[8];
    int t = threadIdx.x;             // 256 threads
    int base = blockIdx.x * SCAN_CHUNK;
    int i0 = base + 2 * t;
    int a = (i0 < n) ? g_deg[i0] : 0;
    int c = (i0 + 1 < n) ? g_deg[i0 + 1] : 0;
    if (i0 < n)     g_dinv[i0]     = rsqrtf((float)(a + 1));
    if (i0 + 1 < n) g_dinv[i0 + 1] = rsqrtf((float)(c + 1));
    int sum2 = a + c;
    int lane = t & 31, wid = t >> 5;
    int v = sum2;
#pragma unroll
    for (int o = 1; o < 32; o <<= 1) {
        int u = __shfl_up_sync(0xFFFFFFFFu, v, o);
        if (lane >= o) v += u;
    }
    if (lane == 31) s_warp[wid] = v;
    __syncthreads();
    if (t < 8) {
        int w = s_warp[t];
#pragma unroll
        for (int o = 1; o < 8; o <<= 1) {
            int u = __shfl_up_sync(0xFFu, w, o);
            if (t >= o) w += u;
        }
        s_warp[t] = w;
    }
    __syncthreads();
    int woff = wid ? s_warp[wid - 1] : 0;
    int incl = v + woff;
    int excl = incl - sum2;
    if (i0 < n)     g_rowstart[i0] = excl;
    if (i0 + 1 < n) g_rowstart[i0 + 1] = excl + a;
    if (t == 255) g_bsum[blockIdx.x] = incl;
}

__global__ void k_scan2(int nb) {
    __shared__ int s_warp[8];
    int t = threadIdx.x;
    int v0 = (t < nb) ? g_bsum[t] : 0;
    int lane = t & 31, wid = t >> 5;
    int v = v0;
#pragma unroll
    for (int o = 1; o < 32; o <<= 1) {
        int u = __shfl_up_sync(0xFFFFFFFFu, v, o);
        if (lane >= o) v += u;
    }
    if (lane == 31) s_warp[wid] = v;
    __syncthreads();
    if (t < 8) {
        int w = s_warp[t];
#pragma unroll
        for (int o = 1; o < 8; o <<= 1) {
            int u = __shfl_up_sync(0xFFu, w, o);
            if (t >= o) w += u;
        }
        s_warp[t] = w;
    }
    __syncthreads();
    int woff = wid ? s_warp[wid - 1] : 0;
    if (t < nb) g_boff[t] = v + woff - v0;   // exclusive
}

__global__ void k_scan3(int n) {
    int i = blockIdx.x * blockDim.x + threadIdx.x;
    if (i < n) {
        int v = g_rowstart[i] + g_boff[i / SCAN_CHUNK];
        g_rowstart[i] = v;
        g_cursor[i] = v;
    }
}

__global__ void k_fill(const int* __restrict__ row, const int* __restrict__ col, int e) {
    int i = blockIdx.x * blockDim.x + threadIdx.x;
    if (i < e) {
        int pos = atomicAdd(&g_cursor[col[i]], 1);
        g_src[pos] = row[i];
    }
}

// ---------------------------------------------------------------------------
// GEMM1: h1s = fp16((x @ W1) * dinv[row])
// Block = 128 rows, 128 threads, thread = 8 rows x 8 cols.
// x tile stored k-major (xs[k][row]) so compute loads are conflict-free LDS.128.
// Tiles live in dynamic smem (50176B > 48KB static limit).
// ---------------------------------------------------------------------------
__global__ void __launch_bounds__(128) k_gemm1(const float* __restrict__ x,
                                               const float* __restrict__ W, int n) {
    extern __shared__ __align__(16) float smem[];
    float (*xs)[132] = (float(*)[132])smem;             // [64][132] k-major
    float (*ws)[64]  = (float(*)[64])(smem + 64 * 132); // [64][64]

    int t = threadIdx.x;
    int rowbase = blockIdx.x * 128;

    const float4* W4 = (const float4*)W;
    float4* ws4 = (float4*)ws;
#pragma unroll
    for (int i = t; i < 1024; i += 128) ws4[i] = W4[i];

    // Load x tile transposed: 128 rows x 16 float4
    const float4* x4 = (const float4*)x;
#pragma unroll
    for (int i = t; i < 2048; i += 128) {
        int r = i >> 4, c4 = i & 15;
        int gr = rowbase + r;
        float4 v = make_float4(0.f, 0.f, 0.f, 0.f);
        if (gr < n) v = x4[gr * 16 + c4];
        xs[c4 * 4 + 0][r] = v.x;
        xs[c4 * 4 + 1][r] = v.y;
        xs[c4 * 4 + 2][r] = v.z;
        xs[c4 * 4 + 3][r] = v.w;
    }
    __syncthreads();

    int tx = t & 7;        // cols tx*8 .. +7
    int ty = t >> 3;       // rows ty*8 .. +7
    float acc[8][8];
#pragma unroll
    for (int a = 0; a < 8; a++)
#pragma unroll
        for (int b = 0; b < 8; b++) acc[a][b] = 0.f;

#pragma unroll 8
    for (int k = 0; k < 64; k++) {
        float4 xa = *(const float4*)&xs[k][ty * 8];
        float4 xb = *(const float4*)&xs[k][ty * 8 + 4];
        float4 w0 = *(const float4*)&ws[k][tx * 8];
        float4 w1 = *(const float4*)&ws[k][tx * 8 + 4];
        float xv[8] = {xa.x, xa.y, xa.z, xa.w, xb.x, xb.y, xb.z, xb.w};
        float wv[8] = {w0.x, w0.y, w0.z, w0.w, w1.x, w1.y, w1.z, w1.w};
#pragma unroll
        for (int rr = 0; rr < 8; rr++)
#pragma unroll
            for (int cc = 0; cc < 8; cc++)
                acc[rr][cc] += xv[rr] * wv[cc];
    }

#pragma unroll
    for (int rr = 0; rr < 8; rr++) {
        int gr = rowbase + ty * 8 + rr;
        if (gr >= n) break;
        float s = g_dinv[gr];
        __half2 o[4];
#pragma unroll
        for (int p = 0; p < 4; p++)
            o[p] = __floats2half2_rn(acc[rr][2 * p] * s, acc[rr][2 * p + 1] * s);
        *(uint4*)&g_h1s[gr * 64 + tx * 8] = *(uint4*)o;   // STG.128
    }
}

// ---------------------------------------------------------------------------
// Aggregation layer 1 (CSR gather, fp16 source, fp32 accumulate):
// agg1[v] = h1s[v] + sum_{u->v} h1s[u]
// One warp per node; lane holds 2 columns (__half2 = 4B). MLP=4 unroll.
// ---------------------------------------------------------------------------
__global__ void k_agg1(int n) {
    int gw = (blockIdx.x * blockDim.x + threadIdx.x) >> 5;
    int lane = threadIdx.x & 31;
    if (gw >= n) return;

    const __half2* h = (const __half2*)g_h1s;
    float2 acc = __half22float2(h[gw * 32 + lane]);   // self loop

    int start = g_rowstart[gw];
    int deg = g_deg[gw];

    for (int j0 = 0; j0 < deg; j0 += 32) {
        int cnt = min(32, deg - j0);
        int src = (lane < cnt) ? g_src[start + j0 + lane] : 0;
        int jj = 0;
        for (; jj + 4 <= cnt; jj += 4) {
            int s0 = __shfl_sync(0xFFFFFFFFu, src, jj);
            int s1 = __shfl_sync(0xFFFFFFFFu, src, jj + 1);
            int s2 = __shfl_sync(0xFFFFFFFFu, src, jj + 2);
            int s3 = __shfl_sync(0xFFFFFFFFu, src, jj + 3);
            float2 v0 = __half22float2(h[s0 * 32 + lane]);
            float2 v1 = __half22float2(h[s1 * 32 + lane]);
            float2 v2 = __half22float2(h[s2 * 32 + lane]);
            float2 v3 = __half22float2(h[s3 * 32 + lane]);
            acc.x += v0.x; acc.y += v0.y;
            acc.x += v1.x; acc.y += v1.y;
            acc.x += v2.x; acc.y += v2.y;
            acc.x += v3.x; acc.y += v3.y;
        }
        for (; jj < cnt; jj++) {
            int s = __shfl_sync(0xFFFFFFFFu, src, jj);
            float2 v = __half22float2(h[s * 32 + lane]);
            acc.x += v.x; acc.y += v.y;
        }
    }
    ((float2*)g_agg1)[gw * 32 + lane] = acc;
}

// ---------------------------------------------------------------------------
// GEMM2: a = relu(agg1*dinv + b1);  h2s = (a @ W2) * dinv  (fp32)
// Block = 128 rows, 128 threads, thread = 8 rows x 4 cols. k-major x tile.
// Static smem: 64*132*4 + 64*32*4 = 41984B < 48KB.
// ---------------------------------------------------------------------------
__global__ void __launch_bounds__(128) k_gemm2(const float* __restrict__ W2,
                                               const float* __restrict__ b1, int n) {
    __shared__ __align__(16) float xs[64][132];
    __shared__ __align__(16) float ws[64][32];

    int t = threadIdx.x;
    int rowbase = blockIdx.x * 128;

    const float4* W4 = (const float4*)W2;
    float4* ws4 = (float4*)ws;
#pragma unroll
    for (int i = t; i < 512; i += 128) ws4[i] = W4[i];

    const float4* a4 = (const float4*)g_agg1;
    const float4* b14 = (const float4*)b1;
#pragma unroll
    for (int i = t; i < 2048; i += 128) {
        int r = i >> 4, c4 = i & 15;
        int gr = rowbase + r;
        float4 v = make_float4(0.f, 0.f, 0.f, 0.f);
        if (gr < n) {
            float4 u = a4[gr * 16 + c4];
            float s = g_dinv[gr];
            float4 bb = b14[c4];
            v.x = fmaxf(fmaf(u.x, s, bb.x), 0.f);
            v.y = fmaxf(fmaf(u.y, s, bb.y), 0.f);
            v.z = fmaxf(fmaf(u.z, s, bb.z), 0.f);
            v.w = fmaxf(fmaf(u.w, s, bb.w), 0.f);
        }
        xs[c4 * 4 + 0][r] = v.x;
        xs[c4 * 4 + 1][r] = v.y;
        xs[c4 * 4 + 2][r] = v.z;
        xs[c4 * 4 + 3][r] = v.w;
    }
    __syncthreads();

    int tx = t & 7;        // cols tx*4 .. +3
    int ty = t >> 3;       // rows ty*8 .. +7
    float acc[8][4];
#pragma unroll
    for (int a = 0; a < 8; a++)
#pragma unroll
        for (int b = 0; b < 4; b++) acc[a][b] = 0.f;

#pragma unroll 8
    for (int k = 0; k < 64; k++) {
        float4 xa = *(const float4*)&xs[k][ty * 8];
        float4 xb = *(const float4*)&xs[k][ty * 8 + 4];
        float4 w0 = *(const float4*)&ws[k][tx * 4];
        float xv[8] = {xa.x, xa.y, xa.z, xa.w, xb.x, xb.y, xb.z, xb.w};
#pragma unroll
        for (int rr = 0; rr < 8; rr++) {
            acc[rr][0] += xv[rr] * w0.x; acc[rr][1] += xv[rr] * w0.y;
            acc[rr][2] += xv[rr] * w0.z; acc[rr][3] += xv[rr] * w0.w;
        }
    }

    float4* h = (float4*)g_h2s;
#pragma unroll
    for (int rr = 0; rr < 8; rr++) {
        int gr = rowbase + ty * 8 + rr;
        if (gr >= n) break;
        float s = g_dinv[gr];
        h[gr * 8 + tx] = make_float4(acc[rr][0] * s, acc[rr][1] * s, acc[rr][2] * s, acc[rr][3] * s);
    }
}

// ---------------------------------------------------------------------------
// Aggregation layer 2 + log_softmax fused. One warp per node, lane = column.
// ---------------------------------------------------------------------------
__global__ void k_agg2_lsm(const float* __restrict__ b2, float* __restrict__ out, int n) {
    int gw = (blockIdx.x * blockDim.x + threadIdx.x) >> 5;
    int lane = threadIdx.x & 31;
    if (gw >= n) return;

    const float* h = g_h2s;
    float acc = h[gw * 32 + lane];             // self loop

    int start = g_rowstart[gw];
    int deg = g_deg[gw];

    for (int j0 = 0; j0 < deg; j0 += 32) {
        int cnt = min(32, deg - j0);
        int src = (lane < cnt) ? g_src[start + j0 + lane] : 0;
        int jj = 0;
        for (; jj + 4 <= cnt; jj += 4) {
            int s0 = __shfl_sync(0xFFFFFFFFu, src, jj);
            int s1 = __shfl_sync(0xFFFFFFFFu, src, jj + 1);
            int s2 = __shfl_sync(0xFFFFFFFFu, src, jj + 2);
            int s3 = __shfl_sync(0xFFFFFFFFu, src, jj + 3);
            acc += h[s0 * 32 + lane];
            acc += h[s1 * 32 + lane];
            acc += h[s2 * 32 + lane];
            acc += h[s3 * 32 + lane];
        }
        for (; jj < cnt; jj++) {
            int s = __shfl_sync(0xFFFFFFFFu, src, jj);
            acc += h[s * 32 + lane];
        }
    }

    float z = fmaf(acc, g_dinv[gw], b2[lane]);
    float m = z;
#pragma unroll
    for (int o = 16; o; o >>= 1) m = fmaxf(m, __shfl_xor_sync(0xFFFFFFFFu, m, o));
    float ex = expf(z - m);
    float s = ex;
#pragma unroll
    for (int o = 16; o; o >>= 1) s += __shfl_xor_sync(0xFFFFFFFFu, s, o);
    out[gw * 32 + lane] = z - m - logf(s);
}

// ---------------------------------------------------------------------------
extern "C" void kernel_launch(void* const* d_in, const int* in_sizes, int n_in,
                              void* d_out, int out_size) {
    const float* x  = (const float*)d_in[0];
    const int*   ei = (const int*)d_in[1];
    const float* W1 = (const float*)d_in[2];
    const float* b1 = (const float*)d_in[3];
    const float* W2 = (const float*)d_in[4];
    const float* b2 = (const float*)d_in[5];
    float* out = (float*)d_out;

    int n = in_sizes[0] / 64;   // 100000
    int e = in_sizes[1] / 2;    // 1600000
    const int* row = ei;        // sources
    const int* col = ei + e;    // targets

    int nb = (n + SCAN_CHUNK - 1) / SCAN_CHUNK;   // 196

    // Raise dynamic smem limit for gemm1 (host attribute call; capture-safe,
    // idempotent, deterministic).
    cudaFuncSetAttribute(k_gemm1, cudaFuncAttributeMaxDynamicSharedMemorySize,
                         GEMM1_SMEM_BYTES);

    k_zero_deg<<<(n + 255) / 256, 256>>>(n);
    k_count<<<(e + 255) / 256, 256>>>(col, e);

    k_scan1<<<nb, 256>>>(n);                       // also computes dinv
    k_scan2<<<1, 256>>>(nb);
    k_scan3<<<(n + 255) / 256, 256>>>(n);
    k_fill<<<(e + 255) / 256, 256>>>(row, col, e);

    k_gemm1<<<(n + 127) / 128, 128, GEMM1_SMEM_BYTES>>>(x, W1, n);
    k_agg1<<<(n + 7) / 8, 256>>>(n);

    k_gemm2<<<(n + 127) / 128, 128>>>(W2, b1, n);
    k_agg2_lsm<<<(n + 7) / 8, 256>>>(b2, out, n);
}

// round 5
// speedup vs baseline: 1.4297x; 1.0127x over previous
#include <cuda_runtime.h>
#include <cuda_fp16.h>

// Problem constants (reference: N=100000, E=1600000, D 64->64->32)
#define NMAX 100000
#define EMAX 1600000
#define SCAN_CHUNK 512

// Scratch (device globals: no allocation allowed)
__device__ int    g_deg[NMAX];        // incoming degree (no self loop)
__device__ float  g_dinv[NMAX];
__device__ int    g_rowstart[NMAX];   // CSR start per target node (CHUNK-LOCAL)
__device__ int    g_cursor[NMAX];     // fill cursors, chunk-local (consumed per launch)
__device__ int    g_src[EMAX];        // CSR: source node per incoming edge
__device__ int    g_bsum[256];
__device__ int    g_boff[256];        // per-chunk global offset
__device__ __half g_h1s[NMAX * 64];   // (x@W1) * dinv[row], fp16 gather source
__device__ float  g_agg1[NMAX * 64];  // self + gathered sum (fp32)
__device__ __half g_h2s[NMAX * 32];   // (relu(...)@W2) * dinv[row], fp16 gather source

// gemm1 dynamic smem: xs[64][132] + ws[64][64]
#define GEMM1_SMEM_BYTES (64 * 132 * 4 + 64 * 64 * 4)

// ---------------------------------------------------------------------------
__global__ void k_count(const int* __restrict__ col, int e) {
    int i = blockIdx.x * blockDim.x + threadIdx.x;
    if (i < e) atomicAdd(&g_deg[col[i]], 1);
}

// ---------------------------------------------------------------------------
// CSR build: chunk-local prefix scan over deg (dinv fused), block-offset table,
// bucketed fill. Global position = local + g_boff[chunk].
// ---------------------------------------------------------------------------
__global__ void k_scan1(int n) {
    __shared__ int s_warp[8];
    int t = threadIdx.x;             // 256 threads
    int base = blockIdx.x * SCAN_CHUNK;
    int i0 = base + 2 * t;
    int a = (i0 < n) ? g_deg[i0] : 0;
    int c = (i0 + 1 < n) ? g_deg[i0 + 1] : 0;
    if (i0 < n)     g_dinv[i0]     = rsqrtf((float)(a + 1));
    if (i0 + 1 < n) g_dinv[i0 + 1] = rsqrtf((float)(c + 1));
    int sum2 = a + c;
    int lane = t & 31, wid = t >> 5;
    int v = sum2;
#pragma unroll
    for (int o = 1; o < 32; o <<= 1) {
        int u = __shfl_up_sync(0xFFFFFFFFu, v, o);
        if (lane >= o) v += u;
    }
    if (lane == 31) s_warp[wid] = v;
    __syncthreads();
    if (t < 8) {
        int w = s_warp[t];
#pragma unroll
        for (int o = 1; o < 8; o <<= 1) {
            int u = __shfl_up_sync(0xFFu, w, o);
            if (t >= o) w += u;
        }
        s_warp[t] = w;
    }
    __syncthreads();
    int woff = wid ? s_warp[wid - 1] : 0;
    int incl = v + woff;
    int excl = incl - sum2;          // chunk-local exclusive prefix
    if (i0 < n)     { g_rowstart[i0] = excl;         g_cursor[i0] = excl; }
    if (i0 + 1 < n) { g_rowstart[i0 + 1] = excl + a; g_cursor[i0 + 1] = excl + a; }
    if (t == 255) g_bsum[blockIdx.x] = incl;
}

__global__ void k_scan2(int nb) {
    __shared__ int s_warp[8];
    int t = threadIdx.x;
    int v0 = (t < nb) ? g_bsum[t] : 0;
    int lane = t & 31, wid = t >> 5;
    int v = v0;
#pragma unroll
    for (int o = 1; o < 32; o <<= 1) {
        int u = __shfl_up_sync(0xFFFFFFFFu, v, o);
        if (lane >= o) v += u;
    }
    if (lane == 31) s_warp[wid] = v;
    __syncthreads();
    if (t < 8) {
        int w = s_warp[t];
#pragma unroll
        for (int o = 1; o < 8; o <<= 1) {
            int u = __shfl_up_sync(0xFFu, w, o);
            if (t >= o) w += u;
        }
        s_warp[t] = w;
    }
    __syncthreads();
    int woff = wid ? s_warp[wid - 1] : 0;
    if (t < nb) g_boff[t] = v + woff - v0;   // exclusive across chunks
}

__global__ void k_fill(const int* __restrict__ row, const int* __restrict__ col, int e) {
    int i = blockIdx.x * blockDim.x + threadIdx.x;
    if (i < e) {
        int c = col[i];
        int pos = atomicAdd(&g_cursor[c], 1) + __ldg(&g_boff[c >> 9]);
        g_src[pos] = row[i];
    }
}

// ---------------------------------------------------------------------------
// GEMM1: h1s = fp16((x @ W1) * dinv[row])
// Block = 128 rows, 128 threads, thread = 8 rows x 8 cols. k-major x tile.
// ---------------------------------------------------------------------------
__global__ void __launch_bounds__(128) k_gemm1(const float* __restrict__ x,
                                               const float* __restrict__ W, int n) {
    extern __shared__ __align__(16) float smem[];
    float (*xs)[132] = (float(*)[132])smem;             // [64][132] k-major
    float (*ws)[64]  = (float(*)[64])(smem + 64 * 132); // [64][64]

    int t = threadIdx.x;
    int rowbase = blockIdx.x * 128;

    const float4* W4 = (const float4*)W;
    float4* ws4 = (float4*)ws;
#pragma unroll
    for (int i = t; i < 1024; i += 128) ws4[i] = W4[i];

    const float4* x4 = (const float4*)x;
#pragma unroll
    for (int i = t; i < 2048; i += 128) {
        int r = i >> 4, c4 = i & 15;
        int gr = rowbase + r;
        float4 v = make_float4(0.f, 0.f, 0.f, 0.f);
        if (gr < n) v = x4[gr * 16 + c4];
        xs[c4 * 4 + 0][r] = v.x;
        xs[c4 * 4 + 1][r] = v.y;
        xs[c4 * 4 + 2][r] = v.z;
        xs[c4 * 4 + 3][r] = v.w;
    }
    __syncthreads();

    int tx = t & 7;        // cols tx*8 .. +7
    int ty = t >> 3;       // rows ty*8 .. +7
    float acc[8][8];
#pragma unroll
    for (int a = 0; a < 8; a++)
#pragma unroll
        for (int b = 0; b < 8; b++) acc[a][b] = 0.f;

#pragma unroll 8
    for (int k = 0; k < 64; k++) {
        float4 xa = *(const float4*)&xs[k][ty * 8];
        float4 xb = *(const float4*)&xs[k][ty * 8 + 4];
        float4 w0 = *(const float4*)&ws[k][tx * 8];
        float4 w1 = *(const float4*)&ws[k][tx * 8 + 4];
        float xv[8] = {xa.x, xa.y, xa.z, xa.w, xb.x, xb.y, xb.z, xb.w};
        float wv[8] = {w0.x, w0.y, w0.z, w0.w, w1.x, w1.y, w1.z, w1.w};
#pragma unroll
        for (int rr = 0; rr < 8; rr++)
#pragma unroll
            for (int cc = 0; cc < 8; cc++)
                acc[rr][cc] += xv[rr] * wv[cc];
    }

#pragma unroll
    for (int rr = 0; rr < 8; rr++) {
        int gr = rowbase + ty * 8 + rr;
        if (gr >= n) break;
        float s = g_dinv[gr];
        __half2 o[4];
#pragma unroll
        for (int p = 0; p < 4; p++)
            o[p] = __floats2half2_rn(acc[rr][2 * p] * s, acc[rr][2 * p + 1] * s);
        *(uint4*)&g_h1s[gr * 64 + tx * 8] = *(uint4*)o;   // STG.128
    }
}

// ---------------------------------------------------------------------------
// Aggregation layer 1 (CSR gather, fp16 source, fp32 accumulate)
// One warp per node; lane holds 2 columns (__half2). MLP=4 unroll.
// ---------------------------------------------------------------------------
__global__ void k_agg1(int n) {
    int gw = (blockIdx.x * blockDim.x + threadIdx.x) >> 5;
    int lane = threadIdx.x & 31;
    if (gw >= n) return;

    const __half2* h = (const __half2*)g_h1s;
    float2 acc = __half22float2(h[gw * 32 + lane]);   // self loop

    int start = g_rowstart[gw] + __ldg(&g_boff[gw >> 9]);
    int deg = g_deg[gw];

    for (int j0 = 0; j0 < deg; j0 += 32) {
        int cnt = min(32, deg - j0);
        int src = (lane < cnt) ? g_src[start + j0 + lane] : 0;
        int jj = 0;
        for (; jj + 4 <= cnt; jj += 4) {
            int s0 = __shfl_sync(0xFFFFFFFFu, src, jj);
            int s1 = __shfl_sync(0xFFFFFFFFu, src, jj + 1);
            int s2 = __shfl_sync(0xFFFFFFFFu, src, jj + 2);
            int s3 = __shfl_sync(0xFFFFFFFFu, src, jj + 3);
            float2 v0 = __half22float2(h[s0 * 32 + lane]);
            float2 v1 = __half22float2(h[s1 * 32 + lane]);
            float2 v2 = __half22float2(h[s2 * 32 + lane]);
            float2 v3 = __half22float2(h[s3 * 32 + lane]);
            acc.x += v0.x; acc.y += v0.y;
            acc.x += v1.x; acc.y += v1.y;
            acc.x += v2.x; acc.y += v2.y;
            acc.x += v3.x; acc.y += v3.y;
        }
        for (; jj < cnt; jj++) {
            int s = __shfl_sync(0xFFFFFFFFu, src, jj);
            float2 v = __half22float2(h[s * 32 + lane]);
            acc.x += v.x; acc.y += v.y;
        }
    }
    ((float2*)g_agg1)[gw * 32 + lane] = acc;
}

// ---------------------------------------------------------------------------
// GEMM2: a = relu(agg1*dinv + b1);  h2s = fp16((a @ W2) * dinv)
// Block = 128 rows, 128 threads, thread = 8 rows x 4 cols. k-major x tile.
// ---------------------------------------------------------------------------
__global__ void __launch_bounds__(128) k_gemm2(const float* __restrict__ W2,
                                               const float* __restrict__ b1, int n) {
    __shared__ __align__(16) float xs[64][132];
    __shared__ __align__(16) float ws[64][32];

    int t = threadIdx.x;
    int rowbase = blockIdx.x * 128;

    const float4* W4 = (const float4*)W2;
    float4* ws4 = (float4*)ws;
#pragma unroll
    for (int i = t; i < 512; i += 128) ws4[i] = W4[i];

    const float4* a4 = (const float4*)g_agg1;
    const float4* b14 = (const float4*)b1;
#pragma unroll
    for (int i = t; i < 2048; i += 128) {
        int r = i >> 4, c4 = i & 15;
        int gr = rowbase + r;
        float4 v = make_float4(0.f, 0.f, 0.f, 0.f);
        if (gr < n) {
            float4 u = a4[gr * 16 + c4];
            float s = g_dinv[gr];
            float4 bb = b14[c4];
            v.x = fmaxf(fmaf(u.x, s, bb.x), 0.f);
            v.y = fmaxf(fmaf(u.y, s, bb.y), 0.f);
            v.z = fmaxf(fmaf(u.z, s, bb.z), 0.f);
            v.w = fmaxf(fmaf(u.w, s, bb.w), 0.f);
        }
        xs[c4 * 4 + 0][r] = v.x;
        xs[c4 * 4 + 1][r] = v.y;
        xs[c4 * 4 + 2][r] = v.z;
        xs[c4 * 4 + 3][r] = v.w;
    }
    __syncthreads();

    int tx = t & 7;        // cols tx*4 .. +3
    int ty = t >> 3;       // rows ty*8 .. +7
    float acc[8][4];
#pragma unroll
    for (int a = 0; a < 8; a++)
#pragma unroll
        for (int b = 0; b < 4; b++) acc[a][b] = 0.f;

#pragma unroll 8
    for (int k = 0; k < 64; k++) {
        float4 xa = *(const float4*)&xs[k][ty * 8];
        float4 xb = *(const float4*)&xs[k][ty * 8 + 4];
        float4 w0 = *(const float4*)&ws[k][tx * 4];
        float xv[8] = {xa.x, xa.y, xa.z, xa.w, xb.x, xb.y, xb.z, xb.w};
#pragma unroll
        for (int rr = 0; rr < 8; rr++) {
            acc[rr][0] += xv[rr] * w0.x; acc[rr][1] += xv[rr] * w0.y;
            acc[rr][2] += xv[rr] * w0.z; acc[rr][3] += xv[rr] * w0.w;
        }
    }

#pragma unroll
    for (int rr = 0; rr < 8; rr++) {
        int gr = rowbase + ty * 8 + rr;
        if (gr >= n) break;
        float s = g_dinv[gr];
        __half2 o[2];
        o[0] = __floats2half2_rn(acc[rr][0] * s, acc[rr][1] * s);
        o[1] = __floats2half2_rn(acc[rr][2] * s, acc[rr][3] * s);
        *(uint2*)&g_h2s[gr * 32 + tx * 4] = *(uint2*)o;   // STG.64
    }
}

// ---------------------------------------------------------------------------
// Aggregation layer 2 + log_softmax fused. One warp per node, lane = column.
// fp16 gather source, fp32 accumulate.
// ---------------------------------------------------------------------------
__global__ void k_agg2_lsm(const float* __restrict__ b2, float* __restrict__ out, int n) {
    int gw = (blockIdx.x * blockDim.x + threadIdx.x) >> 5;
    int lane = threadIdx.x & 31;
    if (gw >= n) return;

    const __half* h = g_h2s;
    float acc = __half2float(h[gw * 32 + lane]);   // self loop

    int start = g_rowstart[gw] + __ldg(&g_boff[gw >> 9]);
    int deg = g_deg[gw];

    for (int j0 = 0; j0 < deg; j0 += 32) {
        int cnt = min(32, deg - j0);
        int src = (lane < cnt) ? g_src[start + j0 + lane] : 0;
        int jj = 0;
        for (; jj + 4 <= cnt; jj += 4) {
            int s0 = __shfl_sync(0xFFFFFFFFu, src, jj);
            int s1 = __shfl_sync(0xFFFFFFFFu, src, jj + 1);
            int s2 = __shfl_sync(0xFFFFFFFFu, src, jj + 2);
            int s3 = __shfl_sync(0xFFFFFFFFu, src, jj + 3);
            float v0 = __half2float(h[s0 * 32 + lane]);
            float v1 = __half2float(h[s1 * 32 + lane]);
            float v2 = __half2float(h[s2 * 32 + lane]);
            float v3 = __half2float(h[s3 * 32 + lane]);
            acc += v0 + v1 + v2 + v3;
        }
        for (; jj < cnt; jj++) {
            int s = __shfl_sync(0xFFFFFFFFu, src, jj);
            acc += __half2float(h[s * 32 + lane]);
        }
    }

    float z = fmaf(acc, g_dinv[gw], b2[lane]);
    float m = z;
#pragma unroll
    for (int o = 16; o; o >>= 1) m = fmaxf(m, __shfl_xor_sync(0xFFFFFFFFu, m, o));
    float ex = expf(z - m);
    float s = ex;
#pragma unroll
    for (int o = 16; o; o >>= 1) s += __shfl_xor_sync(0xFFFFFFFFu, s, o);
    out[gw * 32 + lane] = z - m - logf(s);
}

// ---------------------------------------------------------------------------
extern "C" void kernel_launch(void* const* d_in, const int* in_sizes, int n_in,
                              void* d_out, int out_size) {
    const float* x  = (const float*)d_in[0];
    const int*   ei = (const int*)d_in[1];
    const float* W1 = (const float*)d_in[2];
    const float* b1 = (const float*)d_in[3];
    const float* W2 = (const float*)d_in[4];
    const float* b2 = (const float*)d_in[5];
    float* out = (float*)d_out;

    int n = in_sizes[0] / 64;   // 100000
    int e = in_sizes[1] / 2;    // 1600000
    const int* row = ei;        // sources
    const int* col = ei + e;    // targets

    int nb = (n + SCAN_CHUNK - 1) / SCAN_CHUNK;   // 196

    cudaFuncSetAttribute(k_gemm1, cudaFuncAttributeMaxDynamicSharedMemorySize,
                         GEMM1_SMEM_BYTES);

    // Zero degree array via memset node (cheaper than a kernel launch)
    void* degp = nullptr;
    cudaGetSymbolAddress(&degp, g_deg);
    cudaMemsetAsync(degp, 0, n * sizeof(int));

    k_count<<<(e + 255) / 256, 256>>>(col, e);

    k_scan1<<<nb, 256>>>(n);                       // also computes dinv, cursors
    k_scan2<<<1, 256>>>(nb);
    k_fill<<<(e + 255) / 256, 256>>>(row, col, e);

    k_gemm1<<<(n + 127) / 128, 128, GEMM1_SMEM_BYTES>>>(x, W1, n);
    k_agg1<<<(n + 7) / 8, 256>>>(n);

    k_gemm2<<<(n + 127) / 128, 128>>>(W2, b1, n);
    k_agg2_lsm<<<(n + 7) / 8, 256>>>(b2, out, n);
}

// round 6
// speedup vs baseline: 1.4484x; 1.0131x over previous
#include <cuda_runtime.h>
#include <cuda_fp16.h>

// Problem constants (reference: N=100000, E=1600000, D 64->64->32)
#define NMAX 100000
#define EMAX 1600000
#define SCAN_CHUNK 512

// Scratch (device globals: no allocation allowed)
__device__ int    g_deg[NMAX + 1];    // incoming degree; [NMAX] = global base counter
__device__ float  g_dinv[NMAX];
__device__ int    g_rowstart[NMAX];   // CSR start per target node (global)
__device__ int    g_cursor[NMAX];     // fill cursors (consumed per launch)
__device__ int    g_src[EMAX];        // CSR: source node per incoming edge
__device__ __half g_h1s[NMAX * 64];   // (x@W1) * dinv[row], fp16
__device__ __half g_agg1[NMAX * 64];  // self + gathered sum, fp16
__device__ __half g_h2s[NMAX * 32];   // (relu(...)@W2) * dinv[row], fp16

// gemm1 dynamic smem: xs[64][132] + ws[64][64]
#define GEMM1_SMEM_BYTES (64 * 132 * 4 + 64 * 64 * 4)
#define CNT_EDGES_PER_BLOCK 2048      // 128 threads x 16 edges

// ---------------------------------------------------------------------------
// K1: heterogeneous launch. Blocks [0, gemmBlocks) run GEMM1 tiles
//     (h1s = fp16((x@W1)*dinv... dinv not yet known! see note), blocks
//     [gemmBlocks, ...) count edge in-degrees.
// NOTE: dinv depends on degree counts which finish in THIS launch, so GEMM1
//       here computes h1_raw = x@W1 WITHOUT the dinv scale; the dinv[row]
//       scale is applied in k_scan (which knows deg) -- no: scan is per-node
//       scalar, h1s rows are 64-wide. Instead we fold dinv[row] at GATHER
//       time in agg1? That costs a per-row multiply per edge. Cheaper: apply
//       dinv in k_scan is wrong-shape; so we apply dinv[row] scaling as part
//       of agg1's load: v * dinv[src]. That adds one extra gather of
//       dinv[src] (4B, L1/L2-resident, same src stream as h rows) and 2 FMA
//       per row -- acceptable, and keeps count+gemm1 overlapped.
// Self-loop term in agg1 similarly scaled by dinv[v].
// ---------------------------------------------------------------------------
__global__ void __launch_bounds__(128) k_gemm1_count(const float* __restrict__ x,
                                                     const float* __restrict__ W,
                                                     const int* __restrict__ col,
                                                     int n, int e, int gemmBlocks) {
    if ((int)blockIdx.x >= gemmBlocks) {
        // ---- edge-degree counting ----
        int b = blockIdx.x - gemmBlocks;
        int base = b * CNT_EDGES_PER_BLOCK + threadIdx.x;
#pragma unroll
        for (int j = 0; j < 16; j++) {
            int idx = base + j * 128;
            if (idx < e) atomicAdd(&g_deg[__ldg(&col[idx])], 1);
        }
        return;
    }

    // ---- GEMM1 tile: h1_raw = x @ W1 (fp16 out, no dinv yet) ----
    extern __shared__ __align__(16) float smem[];
    float (*xs)[132] = (float(*)[132])smem;             // [64][132] k-major
    float (*ws)[64]  = (float(*)[64])(smem + 64 * 132); // [64][64]

    int t = threadIdx.x;
    int rowbase = blockIdx.x * 128;

    const float4* W4 = (const float4*)W;
    float4* ws4 = (float4*)ws;
#pragma unroll
    for (int i = t; i < 1024; i += 128) ws4[i] = W4[i];

    const float4* x4 = (const float4*)x;
#pragma unroll
    for (int i = t; i < 2048; i += 128) {
        int r = i >> 4, c4 = i & 15;
        int gr = rowbase + r;
        float4 v = make_float4(0.f, 0.f, 0.f, 0.f);
        if (gr < n) v = x4[gr * 16 + c4];
        xs[c4 * 4 + 0][r] = v.x;
        xs[c4 * 4 + 1][r] = v.y;
        xs[c4 * 4 + 2][r] = v.z;
        xs[c4 * 4 + 3][r] = v.w;
    }
    __syncthreads();

    int tx = t & 7;        // cols tx*8 .. +7
    int ty = t >> 3;       // rows ty*8 .. +7
    float acc[8][8];
#pragma unroll
    for (int a = 0; a < 8; a++)
#pragma unroll
        for (int b = 0; b < 8; b++) acc[a][b] = 0.f;

#pragma unroll 8
    for (int k = 0; k < 64; k++) {
        float4 xa = *(const float4*)&xs[k][ty * 8];
        float4 xb = *(const float4*)&xs[k][ty * 8 + 4];
        float4 w0 = *(const float4*)&ws[k][tx * 8];
        float4 w1 = *(const float4*)&ws[k][tx * 8 + 4];
        float xv[8] = {xa.x, xa.y, xa.z, xa.w, xb.x, xb.y, xb.z, xb.w};
        float wv[8] = {w0.x, w0.y, w0.z, w0.w, w1.x, w1.y, w1.z, w1.w};
#pragma unroll
        for (int rr = 0; rr < 8; rr++)
#pragma unroll
            for (int cc = 0; cc < 8; cc++)
                acc[rr][cc] += xv[rr] * wv[cc];
    }

#pragma unroll
    for (int rr = 0; rr < 8; rr++) {
        int gr = rowbase + ty * 8 + rr;
        if (gr >= n) break;
        __half2 o[4];
#pragma unroll
        for (int p = 0; p < 4; p++)
            o[p] = __floats2half2_rn(acc[rr][2 * p], acc[rr][2 * p + 1]);
        *(uint4*)&g_h1s[gr * 64 + tx * 8] = *(uint4*)o;   // STG.128
    }
}

// ---------------------------------------------------------------------------
// Fused scan: per-chunk local exclusive scan of deg, chunk base via atomicAdd
// on g_deg[NMAX], dinv computed, rowstart+cursor written (global positions).
// ---------------------------------------------------------------------------
__global__ void k_scan(int n) {
    __shared__ int s_warp[8];
    __shared__ int s_base;
    int t = threadIdx.x;             // 256 threads
    int base = blockIdx.x * SCAN_CHUNK;
    int i0 = base + 2 * t;
    int a = (i0 < n) ? g_deg[i0] : 0;
    int c = (i0 + 1 < n) ? g_deg[i0 + 1] : 0;
    if (i0 < n)     g_dinv[i0]     = rsqrtf((float)(a + 1));
    if (i0 + 1 < n) g_dinv[i0 + 1] = rsqrtf((float)(c + 1));
    int sum2 = a + c;
    int lane = t & 31, wid = t >> 5;
    int v = sum2;
#pragma unroll
    for (int o = 1; o < 32; o <<= 1) {
        int u = __shfl_up_sync(0xFFFFFFFFu, v, o);
        if (lane >= o) v += u;
    }
    if (lane == 31) s_warp[wid] = v;
    __syncthreads();
    if (t < 8) {
        int w = s_warp[t];
#pragma unroll
        for (int o = 1; o < 8; o <<= 1) {
            int u = __shfl_up_sync(0xFFu, w, o);
            if (t >= o) w += u;
        }
        s_warp[t] = w;
    }
    __syncthreads();
    int woff = wid ? s_warp[wid - 1] : 0;
    int incl = v + woff;             // inclusive within chunk
    if (t == 255) s_base = atomicAdd(&g_deg[NMAX], incl);  // chunk total = last incl
    __syncthreads();
    int gbase = s_base;
    int excl = incl - sum2 + gbase;  // global exclusive prefix
    if (i0 < n)     { g_rowstart[i0] = excl;         g_cursor[i0] = excl; }
    if (i0 + 1 < n) { g_rowstart[i0 + 1] = excl + a; g_cursor[i0 + 1] = excl + a; }
}

__global__ void k_fill(const int* __restrict__ row, const int* __restrict__ col, int e) {
    int i = blockIdx.x * blockDim.x + threadIdx.x;
    if (i < e) {
        int c = col[i];
        int pos = atomicAdd(&g_cursor[c], 1);
        g_src[pos] = row[i];
    }
}

// ---------------------------------------------------------------------------
// Aggregation layer 1 (CSR gather, fp16 source, fp32 accumulate):
// agg1[v] = dinv[v]*h1raw[v] + sum_{u->v} dinv[u]*h1raw[u]   (fp16 out)
// One warp per node; lane holds 2 columns (__half2). MLP=4 unroll with
// per-source dinv scale (FMA).
// ---------------------------------------------------------------------------
__global__ void k_agg1(int n) {
    int gw = (blockIdx.x * blockDim.x + threadIdx.x) >> 5;
    int lane = threadIdx.x & 31;
    if (gw >= n) return;

    const __half2* h = (const __half2*)g_h1s;
    float dv = g_dinv[gw];
    float2 self = __half22float2(h[gw * 32 + lane]);
    float2 acc = make_float2(self.x * dv, self.y * dv);   // self loop

    int start = g_rowstart[gw];
    int deg = g_deg[gw];

    for (int j0 = 0; j0 < deg; j0 += 32) {
        int cnt = min(32, deg - j0);
        int src = (lane < cnt) ? g_src[start + j0 + lane] : 0;
        int jj = 0;
        for (; jj + 4 <= cnt; jj += 4) {
            int s0 = __shfl_sync(0xFFFFFFFFu, src, jj);
            int s1 = __shfl_sync(0xFFFFFFFFu, src, jj + 1);
            int s2 = __shfl_sync(0xFFFFFFFFu, src, jj + 2);
            int s3 = __shfl_sync(0xFFFFFFFFu, src, jj + 3);
            float d0 = __ldg(&g_dinv[s0]);
            float d1 = __ldg(&g_dinv[s1]);
            float d2 = __ldg(&g_dinv[s2]);
            float d3 = __ldg(&g_dinv[s3]);
            float2 v0 = __half22float2(h[s0 * 32 + lane]);
            float2 v1 = __half22float2(h[s1 * 32 + lane]);
            float2 v2 = __half22float2(h[s2 * 32 + lane]);
            float2 v3 = __half22float2(h[s3 * 32 + lane]);
            acc.x = fmaf(v0.x, d0, acc.x); acc.y = fmaf(v0.y, d0, acc.y);
            acc.x = fmaf(v1.x, d1, acc.x); acc.y = fmaf(v1.y, d1, acc.y);
            acc.x = fmaf(v2.x, d2, acc.x); acc.y = fmaf(v2.y, d2, acc.y);
            acc.x = fmaf(v3.x, d3, acc.x); acc.y = fmaf(v3.y, d3, acc.y);
        }
        for (; jj < cnt; jj++) {
            int s = __shfl_sync(0xFFFFFFFFu, src, jj);
            float d = __ldg(&g_dinv[s]);
            float2 v = __half22float2(h[s * 32 + lane]);
            acc.x = fmaf(v.x, d, acc.x); acc.y = fmaf(v.y, d, acc.y);
        }
    }
    ((__half2*)g_agg1)[gw * 32 + lane] = __floats2half2_rn(acc.x, acc.y);
}

// ---------------------------------------------------------------------------
// GEMM2: a = relu(agg1*dinv + b1);  h2s = fp16((a @ W2) * dinv)
// Block = 128 rows, 128 threads, thread = 8 rows x 4 cols. k-major x tile.
// agg1 read as fp16.
// ---------------------------------------------------------------------------
__global__ void __launch_bounds__(128) k_gemm2(const float* __restrict__ W2,
                                               const float* __restrict__ b1, int n) {
    __shared__ __align__(16) float xs[64][132];
    __shared__ __align__(16) float ws[64][32];

    int t = threadIdx.x;
    int rowbase = blockIdx.x * 128;

    const float4* W4 = (const float4*)W2;
    float4* ws4 = (float4*)ws;
#pragma unroll
    for (int i = t; i < 512; i += 128) ws4[i] = W4[i];

    const uint2* a2 = (const uint2*)g_agg1;   // 4 halfs per uint2
    const float4* b14 = (const float4*)b1;
#pragma unroll
    for (int i = t; i < 2048; i += 128) {
        int r = i >> 4, c4 = i & 15;
        int gr = rowbase + r;
        float4 v = make_float4(0.f, 0.f, 0.f, 0.f);
        if (gr < n) {
            uint2 raw = a2[gr * 16 + c4];
            float2 u01 = __half22float2(*(__half2*)&raw.x);
            float2 u23 = __half22float2(*(__half2*)&raw.y);
            float s = g_dinv[gr];
            float4 bb = b14[c4];
            v.x = fmaxf(fmaf(u01.x, s, bb.x), 0.f);
            v.y = fmaxf(fmaf(u01.y, s, bb.y), 0.f);
            v.z = fmaxf(fmaf(u23.x, s, bb.z), 0.f);
            v.w = fmaxf(fmaf(u23.y, s, bb.w), 0.f);
        }
        xs[c4 * 4 + 0][r] = v.x;
        xs[c4 * 4 + 1][r] = v.y;
        xs[c4 * 4 + 2][r] = v.z;
        xs[c4 * 4 + 3][r] = v.w;
    }
    __syncthreads();

    int tx = t & 7;        // cols tx*4 .. +3
    int ty = t >> 3;       // rows ty*8 .. +7
    float acc[8][4];
#pragma unroll
    for (int a = 0; a < 8; a++)
#pragma unroll
        for (int b = 0; b < 4; b++) acc[a][b] = 0.f;

#pragma unroll 8
    for (int k = 0; k < 64; k++) {
        float4 xa = *(const float4*)&xs[k][ty * 8];
        float4 xb = *(const float4*)&xs[k][ty * 8 + 4];
        float4 w0 = *(const float4*)&ws[k][tx * 4];
        float xv[8] = {xa.x, xa.y, xa.z, xa.w, xb.x, xb.y, xb.z, xb.w};
#pragma unroll
        for (int rr = 0; rr < 8; rr++) {
            acc[rr][0] += xv[rr] * w0.x; acc[rr][1] += xv[rr] * w0.y;
            acc[rr][2] += xv[rr] * w0.z; acc[rr][3] += xv[rr] * w0.w;
        }
    }

#pragma unroll
    for (int rr = 0; rr < 8; rr++) {
        int gr = rowbase + ty * 8 + rr;
        if (gr >= n) break;
        float s = g_dinv[gr];
        __half2 o[2];
        o[0] = __floats2half2_rn(acc[rr][0] * s, acc[rr][1] * s);
        o[1] = __floats2half2_rn(acc[rr][2] * s, acc[rr][3] * s);
        *(uint2*)&g_h2s[gr * 32 + tx * 4] = *(uint2*)o;   // STG.64
    }
}

// ---------------------------------------------------------------------------
// Aggregation layer 2 + log_softmax fused. One warp per node, lane = column.
// ---------------------------------------------------------------------------
__global__ void k_agg2_lsm(const float* __restrict__ b2, float* __restrict__ out, int n) {
    int gw = (blockIdx.x * blockDim.x + threadIdx.x) >> 5;
    int lane = threadIdx.x & 31;
    if (gw >= n) return;

    const __half* h = g_h2s;
    float acc = __half2float(h[gw * 32 + lane]);   // self loop

    int start = g_rowstart[gw];
    int deg = g_deg[gw];

    for (int j0 = 0; j0 < deg; j0 += 32) {
        int cnt = min(32, deg - j0);
        int src = (lane < cnt) ? g_src[start + j0 + lane] : 0;
        int jj = 0;
        for (; jj + 4 <= cnt; jj += 4) {
            int s0 = __shfl_sync(0xFFFFFFFFu, src, jj);
            int s1 = __shfl_sync(0xFFFFFFFFu, src, jj + 1);
            int s2 = __shfl_sync(0xFFFFFFFFu, src, jj + 2);
            int s3 = __shfl_sync(0xFFFFFFFFu, src, jj + 3);
            float v0 = __half2float(h[s0 * 32 + lane]);
            float v1 = __half2float(h[s1 * 32 + lane]);
            float v2 = __half2float(h[s2 * 32 + lane]);
            float v3 = __half2float(h[s3 * 32 + lane]);
            acc += v0 + v1 + v2 + v3;
        }
        for (; jj < cnt; jj++) {
            int s = __shfl_sync(0xFFFFFFFFu, src, jj);
            acc += __half2float(h[s * 32 + lane]);
        }
    }

    float z = fmaf(acc, g_dinv[gw], b2[lane]);
    float m = z;
#pragma unroll
    for (int o = 16; o; o >>= 1) m = fmaxf(m, __shfl_xor_sync(0xFFFFFFFFu, m, o));
    float ex = expf(z - m);
    float s = ex;
#pragma unroll
    for (int o = 16; o; o >>= 1) s += __shfl_xor_sync(0xFFFFFFFFu, s, o);
    out[gw * 32 + lane] = z - m - logf(s);
}

// ---------------------------------------------------------------------------
extern "C" void kernel_launch(void* const* d_in, const int* in_sizes, int n_in,
                              void* d_out, int out_size) {
    const float* x  = (const float*)d_in[0];
    const int*   ei = (const int*)d_in[1];
    const float* W1 = (const float*)d_in[2];
    const float* b1 = (const float*)d_in[3];
    const float* W2 = (const float*)d_in[4];
    const float* b2 = (const float*)d_in[5];
    float* out = (float*)d_out;

    int n = in_sizes[0] / 64;   // 100000
    int e = in_sizes[1] / 2;    // 1600000
    const int* row = ei;        // sources
    const int* col = ei + e;    // targets

    cudaFuncSetAttribute(k_gemm1_count, cudaFuncAttributeMaxDynamicSharedMemorySize,
                         GEMM1_SMEM_BYTES);

    // Zero degree array + global base counter via memset node
    void* degp = nullptr;
    cudaGetSymbolAddress(&degp, g_deg);
    cudaMemsetAsync(degp, 0, (NMAX + 1) * sizeof(int));

    // K1: GEMM1 tiles + degree counting, one heterogeneous launch
    int gemmBlocks = (n + 127) / 128;
    int cntBlocks = (e + CNT_EDGES_PER_BLOCK - 1) / CNT_EDGES_PER_BLOCK;
    k_gemm1_count<<<gemmBlocks + cntBlocks, 128, GEMM1_SMEM_BYTES>>>(x, W1, col, n, e, gemmBlocks);

    int nb = (n + SCAN_CHUNK - 1) / SCAN_CHUNK;   // 196
    k_scan<<<nb, 256>>>(n);                        // scan + dinv + cursors (1 kernel)
    k_fill<<<(e + 255) / 256, 256>>>(row, col, e);

    k_agg1<<<(n + 7) / 8, 256>>>(n);

    k_gemm2<<<(n + 127) / 128, 128>>>(W2, b1, n);
    k_agg2_lsm<<<(n + 7) / 8, 256>>>(b2, out, n);
}

// round 8
// speedup vs baseline: 1.4501x; 1.0012x over previous
#include <cuda_runtime.h>
#include <cuda_fp16.h>

// Problem constants (reference: N=100000, E=1600000, D 64->64->32)
#define NMAX 100000
#define EMAX 1600000
#define SCAN_CHUNK 512

// Scratch (device globals: no allocation allowed)
__device__ int    g_deg[NMAX + 1];    // incoming degree; [NMAX] = global base counter
__device__ float  g_dinv[NMAX];
__device__ int    g_rowstart[NMAX];   // CSR start per target node (global)
__device__ int    g_cursor[NMAX];     // fill cursors (consumed per launch)
__device__ int    g_src[EMAX];        // CSR: source node per incoming edge
__device__ __half g_h1s[NMAX * 64];   // x@W1 (raw), then *dinv[row] after k_scan
__device__ __half g_agg1[NMAX * 64];  // self + gathered sum, fp16
__device__ __half g_h2s[NMAX * 32];   // (relu(...)@W2) * dinv[row], fp16

// gemm1 dynamic smem: xs[64][132] + ws[64][64]
#define GEMM1_SMEM_BYTES (64 * 132 * 4 + 64 * 64 * 4)
#define CNT_EDGES_PER_BLOCK 2048      // 128 threads x 16 edges

// ---------------------------------------------------------------------------
// K1: heterogeneous launch. Blocks [0, gemmBlocks) compute h1raw = x@W1 (fp16);
// blocks >= gemmBlocks count edge in-degrees. dinv scaling of h1s happens in
// k_scan (node-parallel) so agg1 stays a pure-add loop.
// ---------------------------------------------------------------------------
__global__ void __launch_bounds__(128) k_gemm1_count(const float* __restrict__ x,
                                                     const float* __restrict__ W,
                                                     const int* __restrict__ col,
                                                     int n, int e, int gemmBlocks) {
    if ((int)blockIdx.x >= gemmBlocks) {
        int b = blockIdx.x - gemmBlocks;
        int base = b * CNT_EDGES_PER_BLOCK + threadIdx.x;
#pragma unroll
        for (int j = 0; j < 16; j++) {
            int idx = base + j * 128;
            if (idx < e) atomicAdd(&g_deg[__ldg(&col[idx])], 1);
        }
        return;
    }

    extern __shared__ __align__(16) float smem[];
    float (*xs)[132] = (float(*)[132])smem;             // [64][132] k-major
    float (*ws)[64]  = (float(*)[64])(smem + 64 * 132); // [64][64]

    int t = threadIdx.x;
    int rowbase = blockIdx.x * 128;

    const float4* W4 = (const float4*)W;
    float4* ws4 = (float4*)ws;
#pragma unroll
    for (int i = t; i < 1024; i += 128) ws4[i] = W4[i];

    const float4* x4 = (const float4*)x;
#pragma unroll
    for (int i = t; i < 2048; i += 128) {
        int r = i >> 4, c4 = i & 15;
        int gr = rowbase + r;
        float4 v = make_float4(0.f, 0.f, 0.f, 0.f);
        if (gr < n) v = x4[gr * 16 + c4];
        xs[c4 * 4 + 0][r] = v.x;
        xs[c4 * 4 + 1][r] = v.y;
        xs[c4 * 4 + 2][r] = v.z;
        xs[c4 * 4 + 3][r] = v.w;
    }
    __syncthreads();

    int tx = t & 7;        // cols tx*8 .. +7
    int ty = t >> 3;       // rows ty*8 .. +7
    float acc[8][8];
#pragma unroll
    for (int a = 0; a < 8; a++)
#pragma unroll
        for (int b = 0; b < 8; b++) acc[a][b] = 0.f;

#pragma unroll 8
    for (int k = 0; k < 64; k++) {
        float4 xa = *(const float4*)&xs[k][ty * 8];
        float4 xb = *(const float4*)&xs[k][ty * 8 + 4];
        float4 w0 = *(const float4*)&ws[k][tx * 8];
        float4 w1 = *(const float4*)&ws[k][tx * 8 + 4];
        float xv[8] = {xa.x, xa.y, xa.z, xa.w, xb.x, xb.y, xb.z, xb.w};
        float wv[8] = {w0.x, w0.y, w0.z, w0.w, w1.x, w1.y, w1.z, w1.w};
#pragma unroll
        for (int rr = 0; rr < 8; rr++)
#pragma unroll
            for (int cc = 0; cc < 8; cc++)
                acc[rr][cc] += xv[rr] * wv[cc];
    }

#pragma unroll
    for (int rr = 0; rr < 8; rr++) {
        int gr = rowbase + ty * 8 + rr;
        if (gr >= n) break;
        __half2 o[4];
#pragma unroll
        for (int p = 0; p < 4; p++)
            o[p] = __floats2half2_rn(acc[rr][2 * p], acc[rr][2 * p + 1]);
        *(uint4*)&g_h1s[gr * 64 + tx * 8] = *(uint4*)o;   // STG.128
    }
}

// ---------------------------------------------------------------------------
// Fused scan + dinv + h1s scaling:
//  - per-chunk local exclusive scan of deg; chunk base via atomicAdd
//  - dinv computed and kept in smem
//  - h1s rows of this chunk scaled in place by dinv[row]
// ---------------------------------------------------------------------------
__global__ void k_scan(int n) {
    __shared__ int s_warp[8];
    __shared__ int s_base;
    __shared__ float s_dinv[SCAN_CHUNK];
    int t = threadIdx.x;             // 256 threads
    int base = blockIdx.x * SCAN_CHUNK;
    int i0 = base + 2 * t;
    int a = (i0 < n) ? g_deg[i0] : 0;
    int c = (i0 + 1 < n) ? g_deg[i0 + 1] : 0;
    float da = rsqrtf((float)(a + 1));
    float dc = rsqrtf((float)(c + 1));
    s_dinv[2 * t] = da;
    s_dinv[2 * t + 1] = dc;
    if (i0 < n)     g_dinv[i0]     = da;
    if (i0 + 1 < n) g_dinv[i0 + 1] = dc;

    int sum2 = a + c;
    int lane = t & 31, wid = t >> 5;
    int v = sum2;
#pragma unroll
    for (int o = 1; o < 32; o <<= 1) {
        int u = __shfl_up_sync(0xFFFFFFFFu, v, o);
        if (lane >= o) v += u;
    }
    if (lane == 31) s_warp[wid] = v;
    __syncthreads();
    if (t < 8) {
        int w = s_warp[t];
#pragma unroll
        for (int o = 1; o < 8; o <<= 1) {
            int u = __shfl_up_sync(0xFFu, w, o);
            if (t >= o) w += u;
        }
        s_warp[t] = w;
    }
    __syncthreads();
    int woff = wid ? s_warp[wid - 1] : 0;
    int incl = v + woff;             // inclusive within chunk
    if (t == 255) s_base = atomicAdd(&g_deg[NMAX], incl);
    __syncthreads();
    int gbase = s_base;
    int excl = incl - sum2 + gbase;  // global exclusive prefix
    if (i0 < n)     { g_rowstart[i0] = excl;         g_cursor[i0] = excl; }
    if (i0 + 1 < n) { g_rowstart[i0 + 1] = excl + a; g_cursor[i0 + 1] = excl + a; }

    // ---- scale this chunk's h1s rows by dinv[row] (in place) ----
    // 512 rows x 64 halfs = 4096 uint4; 16 per thread.
#pragma unroll
    for (int i = t; i < 4096; i += 256) {
        int rl = i >> 3, c8 = i & 7;
        int node = base + rl;
        if (node >= n) break;        // rows are contiguous; safe early exit
        float s = s_dinv[rl];
        uint4 raw = *(const uint4*)&g_h1s[node * 64 + c8 * 8];
        __half2* hp = (__half2*)&raw;
        __half2 o[4];
#pragma unroll
        for (int p = 0; p < 4; p++) {
            float2 f = __half22float2(hp[p]);
            o[p] = __floats2half2_rn(f.x * s, f.y * s);
        }
        *(uint4*)&g_h1s[node * 64 + c8 * 8] = *(uint4*)o;
    }
}

__global__ void k_fill(const int* __restrict__ row, const int* __restrict__ col, int e) {
    int i = blockIdx.x * blockDim.x + threadIdx.x;
    if (i < e) {
        int c = col[i];
        int pos = atomicAdd(&g_cursor[c], 1);
        g_src[pos] = row[i];
    }
}

// ---------------------------------------------------------------------------
// Aggregation layer 1 (CSR gather, fp16 source, fp32 accumulate, PURE ADD):
// agg1[v] = h1s[v] + sum_{u->v} h1s[u]    (h1s pre-scaled by dinv)
// ---------------------------------------------------------------------------
__global__ void k_agg1(int n) {
    int gw = (blockIdx.x * blockDim.x + threadIdx.x) >> 5;
    int lane = threadIdx.x & 31;
    if (gw >= n) return;

    const __half2* h = (const __half2*)g_h1s;
    float2 acc = __half22float2(h[gw * 32 + lane]);   // self loop (pre-scaled)

    int start = g_rowstart[gw];
    int deg = g_deg[gw];

    for (int j0 = 0; j0 < deg; j0 += 32) {
        int cnt = min(32, deg - j0);
        int src = (lane < cnt) ? g_src[start + j0 + lane] : 0;
        int jj = 0;
        for (; jj + 4 <= cnt; jj += 4) {
            int s0 = __shfl_sync(0xFFFFFFFFu, src, jj);
            int s1 = __shfl_sync(0xFFFFFFFFu, src, jj + 1);
            int s2 = __shfl_sync(0xFFFFFFFFu, src, jj + 2);
            int s3 = __shfl_sync(0xFFFFFFFFu, src, jj + 3);
            float2 v0 = __half22float2(h[s0 * 32 + lane]);
            float2 v1 = __half22float2(h[s1 * 32 + lane]);
            float2 v2 = __half22float2(h[s2 * 32 + lane]);
            float2 v3 = __half22float2(h[s3 * 32 + lane]);
            acc.x += v0.x; acc.y += v0.y;
            acc.x += v1.x; acc.y += v1.y;
            acc.x += v2.x; acc.y += v2.y;
            acc.x += v3.x; acc.y += v3.y;
        }
        for (; jj < cnt; jj++) {
            int s = __shfl_sync(0xFFFFFFFFu, src, jj);
            float2 v = __half22float2(h[s * 32 + lane]);
            acc.x += v.x; acc.y += v.y;
        }
    }
    ((__half2*)g_agg1)[gw * 32 + lane] = __floats2half2_rn(acc.x, acc.y);
}

// ---------------------------------------------------------------------------
// GEMM2: a = relu(agg1*dinv + b1);  h2s = fp16((a @ W2) * dinv)
// ---------------------------------------------------------------------------
__global__ void __launch_bounds__(128) k_gemm2(const float* __restrict__ W2,
                                               const float* __restrict__ b1, int n) {
    __shared__ __align__(16) float xs[64][132];
    __shared__ __align__(16) float ws[64][32];

    int t = threadIdx.x;
    int rowbase = blockIdx.x * 128;

    const float4* W4 = (const float4*)W2;
    float4* ws4 = (float4*)ws;
#pragma unroll
    for (int i = t; i < 512; i += 128) ws4[i] = W4[i];

    const uint2* a2 = (const uint2*)g_agg1;   // 4 halfs per uint2
    const float4* b14 = (const float4*)b1;
#pragma unroll
    for (int i = t; i < 2048; i += 128) {
        int r = i >> 4, c4 = i & 15;
        int gr = rowbase + r;
        float4 v = make_float4(0.f, 0.f, 0.f, 0.f);
        if (gr < n) {
            uint2 raw = a2[gr * 16 + c4];
            float2 u01 = __half22float2(*(__half2*)&raw.x);
            float2 u23 = __half22float2(*(__half2*)&raw.y);
            float s = g_dinv[gr];
            float4 bb = b14[c4];
            v.x = fmaxf(fmaf(u01.x, s, bb.x), 0.f);
            v.y = fmaxf(fmaf(u01.y, s, bb.y), 0.f);
            v.z = fmaxf(fmaf(u23.x, s, bb.z), 0.f);
            v.w = fmaxf(fmaf(u23.y, s, bb.w), 0.f);
        }
        xs[c4 * 4 + 0][r] = v.x;
        xs[c4 * 4 + 1][r] = v.y;
        xs[c4 * 4 + 2][r] = v.z;
        xs[c4 * 4 + 3][r] = v.w;
    }
    __syncthreads();

    int tx = t & 7;        // cols tx*4 .. +3
    int ty = t >> 3;       // rows ty*8 .. +7
    float acc[8][4];
#pragma unroll
    for (int a = 0; a < 8; a++)
#pragma unroll
        for (int b = 0; b < 4; b++) acc[a][b] = 0.f;

#pragma unroll 8
    for (int k = 0; k < 64; k++) {
        float4 xa = *(const float4*)&xs[k][ty * 8];
        float4 xb = *(const float4*)&xs[k][ty * 8 + 4];
        float4 w0 = *(const float4*)&ws[k][tx * 4];
        float xv[8] = {xa.x, xa.y, xa.z, xa.w, xb.x, xb.y, xb.z, xb.w};
#pragma unroll
        for (int rr = 0; rr < 8; rr++) {
            acc[rr][0] += xv[rr] * w0.x; acc[rr][1] += xv[rr] * w0.y;
            acc[rr][2] += xv[rr] * w0.z; acc[rr][3] += xv[rr] * w0.w;
        }
    }

#pragma unroll
    for (int rr = 0; rr < 8; rr++) {
        int gr = rowbase + ty * 8 + rr;
        if (gr >= n) break;
        float s = g_dinv[gr];
        __half2 o[2];
        o[0] = __floats2half2_rn(acc[rr][0] * s, acc[rr][1] * s);
        o[1] = __floats2half2_rn(acc[rr][2] * s, acc[rr][3] * s);
        *(uint2*)&g_h2s[gr * 32 + tx * 4] = *(uint2*)o;   // STG.64
    }
}

// ---------------------------------------------------------------------------
// Aggregation layer 2 + log_softmax fused. One warp per node, lane = column.
// ---------------------------------------------------------------------------
__global__ void k_agg2_lsm(const float* __restrict__ b2, float* __restrict__ out, int n) {
    int gw = (blockIdx.x * blockDim.x + threadIdx.x) >> 5;
    int lane = threadIdx.x & 31;
    if (gw >= n) return;

    const __half* h = g_h2s;
    float acc = __half2float(h[gw * 32 + lane]);   // self loop

    int start = g_rowstart[gw];
    int deg = g_deg[gw];

    for (int j0 = 0; j0 < deg; j0 += 32) {
        int cnt = min(32, deg - j0);
        int src = (lane < cnt) ? g_src[start + j0 + lane] : 0;
        int jj = 0;
        for (; jj + 4 <= cnt; jj += 4) {
            int s0 = __shfl_sync(0xFFFFFFFFu, src, jj);
            int s1 = __shfl_sync(0xFFFFFFFFu, src, jj + 1);
            int s2 = __shfl_sync(0xFFFFFFFFu, src, jj + 2);
            int s3 = __shfl_sync(0xFFFFFFFFu, src, jj + 3);
            float v0 = __half2float(h[s0 * 32 + lane]);
            float v1 = __half2float(h[s1 * 32 + lane]);
            float v2 = __half2float(h[s2 * 32 + lane]);
            float v3 = __half2float(h[s3 * 32 + lane]);
            acc += v0 + v1 + v2 + v3;
        }
        for (; jj < cnt; jj++) {
            int s = __shfl_sync(0xFFFFFFFFu, src, jj);
            acc += __half2float(h[s * 32 + lane]);
        }
    }

    float z = fmaf(acc, g_dinv[gw], b2[lane]);
    float m = z;
#pragma unroll
    for (int o = 16; o; o >>= 1) m = fmaxf(m, __shfl_xor_sync(0xFFFFFFFFu, m, o));
    float ex = expf(z - m);
    float s = ex;
#pragma unroll
    for (int o = 16; o; o >>= 1) s += __shfl_xor_sync(0xFFFFFFFFu, s, o);
    out[gw * 32 + lane] = z - m - logf(s);
}

// ---------------------------------------------------------------------------
extern "C" void kernel_launch(void* const* d_in, const int* in_sizes, int n_in,
                              void* d_out, int out_size) {
    const float* x  = (const float*)d_in[0];
    const int*   ei = (const int*)d_in[1];
    const float* W1 = (const float*)d_in[2];
    const float* b1 = (const float*)d_in[3];
    const float* W2 = (const float*)d_in[4];
    const float* b2 = (const float*)d_in[5];
    float* out = (float*)d_out;

    int n = in_sizes[0] / 64;   // 100000
    int e = in_sizes[1] / 2;    // 1600000
    const int* row = ei;        // sources
    const int* col = ei + e;    // targets

    cudaFuncSetAttribute(k_gemm1_count, cudaFuncAttributeMaxDynamicSharedMemorySize,
                         GEMM1_SMEM_BYTES);

    void* degp = nullptr;
    cudaGetSymbolAddress(&degp, g_deg);
    cudaMemsetAsync(degp, 0, (NMAX + 1) * sizeof(int));

    int gemmBlocks = (n + 127) / 128;
    int cntBlocks = (e + CNT_EDGES_PER_BLOCK - 1) / CNT_EDGES_PER_BLOCK;
    k_gemm1_count<<<gemmBlocks + cntBlocks, 128, GEMM1_SMEM_BYTES>>>(x, W1, col, n, e, gemmBlocks);

    int nb = (n + SCAN_CHUNK - 1) / SCAN_CHUNK;   // 196
    k_scan<<<nb, 256>>>(n);                        // scan + dinv + h1s scaling
    k_fill<<<(e + 255) / 256, 256>>>(row, col, e);

    k_agg1<<<(n + 7) / 8, 256>>>(n);

    k_gemm2<<<(n + 127) / 128, 128>>>(W2, b1, n);
    k_agg2_lsm<<<(n + 7) / 8, 256>>>(b2, out, n);
}

// round 10
// speedup vs baseline: 1.5881x; 1.0952x over previous
#include <cuda_runtime.h>
#include <cuda_fp16.h>

// Problem constants (reference: N=100000, E=1600000, D 64->64->32)
#define NMAX 100000
#define EMAX 1600000
#define SCAN_CHUNK 512

// Scratch (device globals: no allocation allowed)
__device__ int    g_deg[NMAX + 1];    // incoming degree; [NMAX] = global base counter
__device__ float  g_dinv[NMAX];
__device__ int    g_rowstart[NMAX];   // CSR start per target node (global)
__device__ int    g_cursor[NMAX];     // fill cursors (consumed per launch)
__device__ int    g_src[EMAX];        // CSR: source node per incoming edge
__device__ __half g_h1s[NMAX * 64];   // x@W1, *dinv[row] applied in k_scan
__device__ __half g_agg1[NMAX * 64];  // self + gathered sum, fp16
__device__ __half g_h2s[NMAX * 32];   // (relu(...)@W2) * dinv[row], fp16

#define GEMM1_SMEM_BYTES (64 * 132 * 4 + 64 * 64 * 4)
#define CNT_EDGES_PER_BLOCK 2048      // 128 threads x 16 edges

// ---------------------------------------------------------------------------
// K1: heterogeneous launch: GEMM1 tiles + degree counting.
// ---------------------------------------------------------------------------
__global__ void __launch_bounds__(128) k_gemm1_count(const float* __restrict__ x,
                                                     const float* __restrict__ W,
                                                     const int* __restrict__ col,
                                                     int n, int e, int gemmBlocks) {
    if ((int)blockIdx.x >= gemmBlocks) {
        int b = blockIdx.x - gemmBlocks;
        int base = b * CNT_EDGES_PER_BLOCK + threadIdx.x;
#pragma unroll
        for (int j = 0; j < 16; j++) {
            int idx = base + j * 128;
            if (idx < e) atomicAdd(&g_deg[__ldg(&col[idx])], 1);
        }
        return;
    }

    extern __shared__ __align__(16) float smem[];
    float (*xs)[132] = (float(*)[132])smem;             // [64][132] k-major
    float (*ws)[64]  = (float(*)[64])(smem + 64 * 132); // [64][64]

    int t = threadIdx.x;
    int rowbase = blockIdx.x * 128;

    const float4* W4 = (const float4*)W;
    float4* ws4 = (float4*)ws;
#pragma unroll
    for (int i = t; i < 1024; i += 128) ws4[i] = W4[i];

    const float4* x4 = (const float4*)x;
#pragma unroll
    for (int i = t; i < 2048; i += 128) {
        int r = i >> 4, c4 = i & 15;
        int gr = rowbase + r;
        float4 v = make_float4(0.f, 0.f, 0.f, 0.f);
        if (gr < n) v = x4[gr * 16 + c4];
        xs[c4 * 4 + 0][r] = v.x;
        xs[c4 * 4 + 1][r] = v.y;
        xs[c4 * 4 + 2][r] = v.z;
        xs[c4 * 4 + 3][r] = v.w;
    }
    __syncthreads();

    int tx = t & 7;
    int ty = t >> 3;
    float acc[8][8];
#pragma unroll
    for (int a = 0; a < 8; a++)
#pragma unroll
        for (int b = 0; b < 8; b++) acc[a][b] = 0.f;

#pragma unroll 8
    for (int k = 0; k < 64; k++) {
        float4 xa = *(const float4*)&xs[k][ty * 8];
        float4 xb = *(const float4*)&xs[k][ty * 8 + 4];
        float4 w0 = *(const float4*)&ws[k][tx * 8];
        float4 w1 = *(const float4*)&ws[k][tx * 8 + 4];
        float xv[8] = {xa.x, xa.y, xa.z, xa.w, xb.x, xb.y, xb.z, xb.w};
        float wv[8] = {w0.x, w0.y, w0.z, w0.w, w1.x, w1.y, w1.z, w1.w};
#pragma unroll
        for (int rr = 0; rr < 8; rr++)
#pragma unroll
            for (int cc = 0; cc < 8; cc++)
                acc[rr][cc] += xv[rr] * wv[cc];
    }

#pragma unroll
    for (int rr = 0; rr < 8; rr++) {
        int gr = rowbase + ty * 8 + rr;
        if (gr >= n) break;
        __half2 o[4];
#pragma unroll
        for (int p = 0; p < 4; p++)
            o[p] = __floats2half2_rn(acc[rr][2 * p], acc[rr][2 * p + 1]);
        *(uint4*)&g_h1s[gr * 64 + tx * 8] = *(uint4*)o;   // STG.128
    }
}

// ---------------------------------------------------------------------------
// Fused scan + dinv + in-place h1s dinv scaling.
// ---------------------------------------------------------------------------
__global__ void k_scan(int n) {
    __shared__ int s_warp[8];
    __shared__ int s_base;
    __shared__ float s_dinv[SCAN_CHUNK];
    int t = threadIdx.x;             // 256 threads
    int base = blockIdx.x * SCAN_CHUNK;
    int i0 = base + 2 * t;
    int a = (i0 < n) ? g_deg[i0] : 0;
    int c = (i0 + 1 < n) ? g_deg[i0 + 1] : 0;
    float da = rsqrtf((float)(a + 1));
    float dc = rsqrtf((float)(c + 1));
    s_dinv[2 * t] = da;
    s_dinv[2 * t + 1] = dc;
    if (i0 < n)     g_dinv[i0]     = da;
    if (i0 + 1 < n) g_dinv[i0 + 1] = dc;

    int sum2 = a + c;
    int lane = t & 31, wid = t >> 5;
    int v = sum2;
#pragma unroll
    for (int o = 1; o < 32; o <<= 1) {
        int u = __shfl_up_sync(0xFFFFFFFFu, v, o);
        if (lane >= o) v += u;
    }
    if (lane == 31) s_warp[wid] = v;
    __syncthreads();
    if (t < 8) {
        int w = s_warp[t];
#pragma unroll
        for (int o = 1; o < 8; o <<= 1) {
            int u = __shfl_up_sync(0xFFu, w, o);
            if (t >= o) w += u;
        }
        s_warp[t] = w;
    }
    __syncthreads();
    int woff = wid ? s_warp[wid - 1] : 0;
    int incl = v + woff;
    if (t == 255) s_base = atomicAdd(&g_deg[NMAX], incl);
    __syncthreads();
    int gbase = s_base;
    int excl = incl - sum2 + gbase;
    if (i0 < n)     { g_rowstart[i0] = excl;         g_cursor[i0] = excl; }
    if (i0 + 1 < n) { g_rowstart[i0 + 1] = excl + a; g_cursor[i0 + 1] = excl + a; }

#pragma unroll
    for (int i = t; i < 4096; i += 256) {
        int rl = i >> 3, c8 = i & 7;
        int node = base + rl;
        if (node >= n) break;
        float s = s_dinv[rl];
        uint4 raw = *(const uint4*)&g_h1s[node * 64 + c8 * 8];
        __half2* hp = (__half2*)&raw;
        __half2 o[4];
#pragma unroll
        for (int p = 0; p < 4; p++) {
            float2 f = __half22float2(hp[p]);
            o[p] = __floats2half2_rn(f.x * s, f.y * s);
        }
        *(uint4*)&g_h1s[node * 64 + c8 * 8] = *(uint4*)o;
    }
}

__global__ void k_fill(const int* __restrict__ row, const int* __restrict__ col, int e) {
    int i = blockIdx.x * blockDim.x + threadIdx.x;
    if (i < e) {
        int c = col[i];
        int pos = atomicAdd(&g_cursor[c], 1);
        g_src[pos] = row[i];
    }
}

// ---------------------------------------------------------------------------
// Aggregation layer 1: LDG.128 lane-group gather, fp16 (HADD2) accumulate.
// Warp per node. grp=lane>>3 selects 1 of 4 sources per step; sub=lane&7
// selects the 16B column chunk (cols sub*8..+7).
// agg1[v] = h1s[v] + sum h1s[u]   (h1s pre-scaled by dinv)
// ---------------------------------------------------------------------------
__global__ void k_agg1(int n) {
    int gw = (blockIdx.x * blockDim.x + threadIdx.x) >> 5;
    int lane = threadIdx.x & 31;
    if (gw >= n) return;

    int grp = lane >> 3;    // 0..3
    int sub = lane & 7;     // 0..7

    // Self-loop row loaded once into group 0's accumulators.
    __half2 acc[4];
    if (grp == 0) {
        uint4 raw = *(const uint4*)&g_h1s[gw * 64 + sub * 8];
        __half2* hp = (__half2*)&raw;
        acc[0] = hp[0]; acc[1] = hp[1]; acc[2] = hp[2]; acc[3] = hp[3];
    } else {
        __half2 z = __floats2half2_rn(0.f, 0.f);
        acc[0] = z; acc[1] = z; acc[2] = z; acc[3] = z;
    }

    int start = g_rowstart[gw];
    int deg = g_deg[gw];

    for (int j0 = 0; j0 < deg; j0 += 32) {
        int cnt = min(32, deg - j0);
        int src = (lane < cnt) ? g_src[start + j0 + lane] : 0;
        for (int jj = 0; jj < cnt; jj += 4) {
            int sidx = jj + grp;
            int s = __shfl_sync(0xFFFFFFFFu, src, sidx);
            if (sidx < cnt) {
                uint4 raw = *(const uint4*)&g_h1s[s * 64 + sub * 8];
                __half2* hp = (__half2*)&raw;
                acc[0] = __hadd2(acc[0], hp[0]);
                acc[1] = __hadd2(acc[1], hp[1]);
                acc[2] = __hadd2(acc[2], hp[2]);
                acc[3] = __hadd2(acc[3], hp[3]);
            }
        }
    }

    // Reduce the 4 lane-groups (lanes l, l^8, l^16).
#pragma unroll
    for (int o = 8; o <= 16; o <<= 1) {
#pragma unroll
        for (int p = 0; p < 4; p++) {
            unsigned u = __shfl_xor_sync(0xFFFFFFFFu,
                                         *(unsigned*)&acc[p], o);
            acc[p] = __hadd2(acc[p], *(__half2*)&u);
        }
    }

    if (lane < 8)
        *(uint4*)&g_agg1[gw * 64 + lane * 8] = *(uint4*)acc;   // 128B row
}

// ---------------------------------------------------------------------------
// GEMM2: a = relu(agg1*dinv + b1);  h2s = fp16((a @ W2) * dinv)
// ---------------------------------------------------------------------------
__global__ void __launch_bounds__(128) k_gemm2(const float* __restrict__ W2,
                                               const float* __restrict__ b1, int n) {
    __shared__ __align__(16) float xs[64][132];
    __shared__ __align__(16) float ws[64][32];

    int t = threadIdx.x;
    int rowbase = blockIdx.x * 128;

    const float4* W4 = (const float4*)W2;
    float4* ws4 = (float4*)ws;
#pragma unroll
    for (int i = t; i < 512; i += 128) ws4[i] = W4[i];

    const uint2* a2 = (const uint2*)g_agg1;
    const float4* b14 = (const float4*)b1;
#pragma unroll
    for (int i = t; i < 2048; i += 128) {
        int r = i >> 4, c4 = i & 15;
        int gr = rowbase + r;
        float4 v = make_float4(0.f, 0.f, 0.f, 0.f);
        if (gr < n) {
            uint2 raw = a2[gr * 16 + c4];
            float2 u01 = __half22float2(*(__half2*)&raw.x);
            float2 u23 = __half22float2(*(__half2*)&raw.y);
            float s = g_dinv[gr];
            float4 bb = b14[c4];
            v.x = fmaxf(fmaf(u01.x, s, bb.x), 0.f);
            v.y = fmaxf(fmaf(u01.y, s, bb.y), 0.f);
            v.z = fmaxf(fmaf(u23.x, s, bb.z), 0.f);
            v.w = fmaxf(fmaf(u23.y, s, bb.w), 0.f);
        }
        xs[c4 * 4 + 0][r] = v.x;
        xs[c4 * 4 + 1][r] = v.y;
        xs[c4 * 4 + 2][r] = v.z;
        xs[c4 * 4 + 3][r] = v.w;
    }
    __syncthreads();

    int tx = t & 7;
    int ty = t >> 3;
    float acc[8][4];
#pragma unroll
    for (int a = 0; a < 8; a++)
#pragma unroll
        for (int b = 0; b < 4; b++) acc[a][b] = 0.f;

#pragma unroll 8
    for (int k = 0; k < 64; k++) {
        float4 xa = *(const float4*)&xs[k][ty * 8];
        float4 xb = *(const float4*)&xs[k][ty * 8 + 4];
        float4 w0 = *(const float4*)&ws[k][tx * 4];
        float xv[8] = {xa.x, xa.y, xa.z, xa.w, xb.x, xb.y, xb.z, xb.w};
#pragma unroll
        for (int rr = 0; rr < 8; rr++) {
            acc[rr][0] += xv[rr] * w0.x; acc[rr][1] += xv[rr] * w0.y;
            acc[rr][2] += xv[rr] * w0.z; acc[rr][3] += xv[rr] * w0.w;
        }
    }

#pragma unroll
    for (int rr = 0; rr < 8; rr++) {
        int gr = rowbase + ty * 8 + rr;
        if (gr >= n) break;
        float s = g_dinv[gr];
        __half2 o[2];
        o[0] = __floats2half2_rn(acc[rr][0] * s, acc[rr][1] * s);
        o[1] = __floats2half2_rn(acc[rr][2] * s, acc[rr][3] * s);
        *(uint2*)&g_h2s[gr * 32 + tx * 4] = *(uint2*)o;
    }
}

// ---------------------------------------------------------------------------
// Aggregation layer 2 + log_softmax. LDG.128 gather: rows are 64B, so
// 4 lanes/row and 8 sources per step. grp=lane>>2, sub=lane&3.
// After reduce, redistribute via 64B smem per warp for the softmax.
// ---------------------------------------------------------------------------
__global__ void k_agg2_lsm(const float* __restrict__ b2, float* __restrict__ out, int n) {
    __shared__ __align__(16) __half s_red[8][32];   // 8 warps x 32 cols

    int warp = threadIdx.x >> 5;
    int gw = (blockIdx.x * blockDim.x + threadIdx.x) >> 5;
    int lane = threadIdx.x & 31;
    if (gw >= n) return;

    int grp = lane >> 2;    // 0..7
    int sub = lane & 3;     // 0..3: cols sub*8..+7

    __half2 acc[4];
    if (grp == 0) {
        uint4 raw = *(const uint4*)&g_h2s[gw * 32 + sub * 8];
        __half2* hp = (__half2*)&raw;
        acc[0] = hp[0]; acc[1] = hp[1]; acc[2] = hp[2]; acc[3] = hp[3];
    } else {
        __half2 z = __floats2half2_rn(0.f, 0.f);
        acc[0] = z; acc[1] = z; acc[2] = z; acc[3] = z;
    }

    int start = g_rowstart[gw];
    int deg = g_deg[gw];

    for (int j0 = 0; j0 < deg; j0 += 32) {
        int cnt = min(32, deg - j0);
        int src = (lane < cnt) ? g_src[start + j0 + lane] : 0;
        for (int jj = 0; jj < cnt; jj += 8) {
            int sidx = jj + grp;
            int s = __shfl_sync(0xFFFFFFFFu, src, sidx);
            if (sidx < cnt) {
                uint4 raw = *(const uint4*)&g_h2s[s * 32 + sub * 8];
                __half2* hp = (__half2*)&raw;
                acc[0] = __hadd2(acc[0], hp[0]);
                acc[1] = __hadd2(acc[1], hp[1]);
                acc[2] = __hadd2(acc[2], hp[2]);
                acc[3] = __hadd2(acc[3], hp[3]);
            }
        }
    }

    // Reduce the 8 lane-groups (xor 4, 8, 16).
#pragma unroll
    for (int o = 4; o <= 16; o <<= 1) {
#pragma unroll
        for (int p = 0; p < 4; p++) {
            unsigned u = __shfl_xor_sync(0xFFFFFFFFu,
                                         *(unsigned*)&acc[p], o);
            acc[p] = __hadd2(acc[p], *(__half2*)&u);
        }
    }

    if (lane < 4)
        *(uint4*)&s_red[warp][lane * 8] = *(uint4*)acc;
    __syncwarp();

    float z = fmaf(__half2float(s_red[warp][lane]), g_dinv[gw], b2[lane]);
    float m = z;
#pragma unroll
    for (int o = 16; o; o >>= 1) m = fmaxf(m, __shfl_xor_sync(0xFFFFFFFFu, m, o));
    float ex = expf(z - m);
    float s = ex;
#pragma unroll
    for (int o = 16; o; o >>= 1) s += __shfl_xor_sync(0xFFFFFFFFu, s, o);
    out[gw * 32 + lane] = z - m - logf(s);
}

// ---------------------------------------------------------------------------
extern "C" void kernel_launch(void* const* d_in, const int* in_sizes, int n_in,
                              void* d_out, int out_size) {
    const float* x  = (const float*)d_in[0];
    const int*   ei = (const int*)d_in[1];
    const float* W1 = (const float*)d_in[2];
    const float* b1 = (const float*)d_in[3];
    const float* W2 = (const float*)d_in[4];
    const float* b2 = (const float*)d_in[5];
    float* out = (float*)d_out;

    int n = in_sizes[0] / 64;   // 100000
    int e = in_sizes[1] / 2;    // 1600000
    const int* row = ei;        // sources
    const int* col = ei + e;    // targets

    cudaFuncSetAttribute(k_gemm1_count, cudaFuncAttributeMaxDynamicSharedMemorySize,
                         GEMM1_SMEM_BYTES);

    void* degp = nullptr;
    cudaGetSymbolAddress(&degp, g_deg);
    cudaMemsetAsync(degp, 0, (NMAX + 1) * sizeof(int));

    int gemmBlocks = (n + 127) / 128;
    int cntBlocks = (e + CNT_EDGES_PER_BLOCK - 1) / CNT_EDGES_PER_BLOCK;
    k_gemm1_count<<<gemmBlocks + cntBlocks, 128, GEMM1_SMEM_BYTES>>>(x, W1, col, n, e, gemmBlocks);

    int nb = (n + SCAN_CHUNK - 1) / SCAN_CHUNK;   // 196
    k_scan<<<nb, 256>>>(n);
    k_fill<<<(e + 255) / 256, 256>>>(row, col, e);

    k_agg1<<<(n + 7) / 8, 256>>>(n);

    k_gemm2<<<(n + 127) / 128, 128>>>(W2, b1, n);
    k_agg2_lsm<<<(n + 7) / 8, 256>>>(b2, out, n);
}

// round 11
// speedup vs baseline: 1.6109x; 1.0143x over previous
#include <cuda_runtime.h>
#include <cuda_fp16.h>

// Problem constants (reference: N=100000, E=1600000, D 64->64->32)
#define NMAX 100000
#define EMAX 1600000
#define SCAN_CHUNK 512

// Scratch (device globals: no allocation allowed)
__device__ int    g_deg[NMAX + 1];    // incoming degree; [NMAX] = global base counter
__device__ float  g_dinv[NMAX];
__device__ int    g_rowstart[NMAX];   // CSR start per target node (global)
__device__ int    g_cursor[NMAX];     // fill cursors (consumed per launch)
__device__ int    g_src[EMAX];        // CSR: source node per incoming edge
__device__ __half g_h1s[NMAX * 64];   // x@W1, *dinv[row] applied in k_scan
__device__ __half g_agg1[NMAX * 64];  // self + gathered sum, fp16
__device__ __half g_h2s[NMAX * 32];   // (relu(...)@W2) * dinv[row], fp16

#define GEMM1_SMEM_BYTES (64 * 132 * 4 + 64 * 64 * 4)
#define CNT_EDGES_PER_BLOCK 2048      // 128 threads x 16 edges

// ---------------------------------------------------------------------------
// K1: heterogeneous launch: GEMM1 tiles + degree counting.
// ---------------------------------------------------------------------------
__global__ void __launch_bounds__(128) k_gemm1_count(const float* __restrict__ x,
                                                     const float* __restrict__ W,
                                                     const int* __restrict__ col,
                                                     int n, int e, int gemmBlocks) {
    if ((int)blockIdx.x >= gemmBlocks) {
        int b = blockIdx.x - gemmBlocks;
        int base = b * CNT_EDGES_PER_BLOCK + threadIdx.x;
#pragma unroll
        for (int j = 0; j < 16; j++) {
            int idx = base + j * 128;
            if (idx < e) atomicAdd(&g_deg[__ldg(&col[idx])], 1);
        }
        return;
    }

    extern __shared__ __align__(16) float smem[];
    float (*xs)[132] = (float(*)[132])smem;             // [64][132] k-major
    float (*ws)[64]  = (float(*)[64])(smem + 64 * 132); // [64][64]

    int t = threadIdx.x;
    int rowbase = blockIdx.x * 128;

    const float4* W4 = (const float4*)W;
    float4* ws4 = (float4*)ws;
#pragma unroll
    for (int i = t; i < 1024; i += 128) ws4[i] = W4[i];

    const float4* x4 = (const float4*)x;
#pragma unroll
    for (int i = t; i < 2048; i += 128) {
        int r = i >> 4, c4 = i & 15;
        int gr = rowbase + r;
        float4 v = make_float4(0.f, 0.f, 0.f, 0.f);
        if (gr < n) v = x4[gr * 16 + c4];
        xs[c4 * 4 + 0][r] = v.x;
        xs[c4 * 4 + 1][r] = v.y;
        xs[c4 * 4 + 2][r] = v.z;
        xs[c4 * 4 + 3][r] = v.w;
    }
    __syncthreads();

    int tx = t & 7;
    int ty = t >> 3;
    float acc[8][8];
#pragma unroll
    for (int a = 0; a < 8; a++)
#pragma unroll
        for (int b = 0; b < 8; b++) acc[a][b] = 0.f;

#pragma unroll 8
    for (int k = 0; k < 64; k++) {
        float4 xa = *(const float4*)&xs[k][ty * 8];
        float4 xb = *(const float4*)&xs[k][ty * 8 + 4];
        float4 w0 = *(const float4*)&ws[k][tx * 8];
        float4 w1 = *(const float4*)&ws[k][tx * 8 + 4];
        float xv[8] = {xa.x, xa.y, xa.z, xa.w, xb.x, xb.y, xb.z, xb.w};
        float wv[8] = {w0.x, w0.y, w0.z, w0.w, w1.x, w1.y, w1.z, w1.w};
#pragma unroll
        for (int rr = 0; rr < 8; rr++)
#pragma unroll
            for (int cc = 0; cc < 8; cc++)
                acc[rr][cc] += xv[rr] * wv[cc];
    }

#pragma unroll
    for (int rr = 0; rr < 8; rr++) {
        int gr = rowbase + ty * 8 + rr;
        if (gr >= n) break;
        __half2 o[4];
#pragma unroll
        for (int p = 0; p < 4; p++)
            o[p] = __floats2half2_rn(acc[rr][2 * p], acc[rr][2 * p + 1]);
        *(uint4*)&g_h1s[gr * 64 + tx * 8] = *(uint4*)o;   // STG.128
    }
}

// ---------------------------------------------------------------------------
// Fused scan + dinv + in-place h1s dinv scaling.
// ---------------------------------------------------------------------------
__global__ void k_scan(int n) {
    __shared__ int s_warp[8];
    __shared__ int s_base;
    __shared__ float s_dinv[SCAN_CHUNK];
    int t = threadIdx.x;             // 256 threads
    int base = blockIdx.x * SCAN_CHUNK;
    int i0 = base + 2 * t;
    int a = (i0 < n) ? g_deg[i0] : 0;
    int c = (i0 + 1 < n) ? g_deg[i0 + 1] : 0;
    float da = rsqrtf((float)(a + 1));
    float dc = rsqrtf((float)(c + 1));
    s_dinv[2 * t] = da;
    s_dinv[2 * t + 1] = dc;
    if (i0 < n)     g_dinv[i0]     = da;
    if (i0 + 1 < n) g_dinv[i0 + 1] = dc;

    int sum2 = a + c;
    int lane = t & 31, wid = t >> 5;
    int v = sum2;
#pragma unroll
    for (int o = 1; o < 32; o <<= 1) {
        int u = __shfl_up_sync(0xFFFFFFFFu, v, o);
        if (lane >= o) v += u;
    }
    if (lane == 31) s_warp[wid] = v;
    __syncthreads();
    if (t < 8) {
        int w = s_warp[t];
#pragma unroll
        for (int o = 1; o < 8; o <<= 1) {
            int u = __shfl_up_sync(0xFFu, w, o);
            if (t >= o) w += u;
        }
        s_warp[t] = w;
    }
    __syncthreads();
    int woff = wid ? s_warp[wid - 1] : 0;
    int incl = v + woff;
    if (t == 255) s_base = atomicAdd(&g_deg[NMAX], incl);
    __syncthreads();
    int gbase = s_base;
    int excl = incl - sum2 + gbase;
    if (i0 < n)     { g_rowstart[i0] = excl;         g_cursor[i0] = excl; }
    if (i0 + 1 < n) { g_rowstart[i0 + 1] = excl + a; g_cursor[i0 + 1] = excl + a; }

#pragma unroll
    for (int i = t; i < 4096; i += 256) {
        int rl = i >> 3, c8 = i & 7;
        int node = base + rl;
        if (node >= n) break;
        float s = s_dinv[rl];
        uint4 raw = *(const uint4*)&g_h1s[node * 64 + c8 * 8];
        __half2* hp = (__half2*)&raw;
        __half2 o[4];
#pragma unroll
        for (int p = 0; p < 4; p++) {
            float2 f = __half22float2(hp[p]);
            o[p] = __floats2half2_rn(f.x * s, f.y * s);
        }
        *(uint4*)&g_h1s[node * 64 + c8 * 8] = *(uint4*)o;
    }
}

// ---------------------------------------------------------------------------
// CSR fill: 4 edges per thread, all loads/atomics/stores independent (MLP=4).
// ---------------------------------------------------------------------------
__global__ void k_fill(const int* __restrict__ row, const int* __restrict__ col, int e) {
    int base = blockIdx.x * 1024 + threadIdx.x;
    int idx[4], pos[4], rv[4];
#pragma unroll
    for (int j = 0; j < 4; j++) {
        int i = base + j * 256;
        idx[j] = i;
        if (i < e) {
            int c = col[i];
            pos[j] = atomicAdd(&g_cursor[c], 1);
            rv[j] = row[i];
        }
    }
#pragma unroll
    for (int j = 0; j < 4; j++)
        if (idx[j] < e) g_src[pos[j]] = rv[j];
}

// ---------------------------------------------------------------------------
// Aggregation layer 1: LDG.128 lane-group gather, fp16 (HADD2) accumulate.
// Warp per node; grp=lane>>3 (4 rows/step), sub=lane&7 (16B chunk).
// Inner loop unrolled x2: 8 sources in flight per iteration.
// ---------------------------------------------------------------------------
__global__ void k_agg1(int n) {
    int gw = (blockIdx.x * blockDim.x + threadIdx.x) >> 5;
    int lane = threadIdx.x & 31;
    if (gw >= n) return;

    int grp = lane >> 3;    // 0..3
    int sub = lane & 7;     // 0..7

    __half2 acc[4];
    if (grp == 0) {
        uint4 raw = *(const uint4*)&g_h1s[gw * 64 + sub * 8];
        __half2* hp = (__half2*)&raw;
        acc[0] = hp[0]; acc[1] = hp[1]; acc[2] = hp[2]; acc[3] = hp[3];
    } else {
        __half2 z = __floats2half2_rn(0.f, 0.f);
        acc[0] = z; acc[1] = z; acc[2] = z; acc[3] = z;
    }

    int start = g_rowstart[gw];
    int deg = g_deg[gw];

    for (int j0 = 0; j0 < deg; j0 += 32) {
        int cnt = min(32, deg - j0);
        int src = (lane < cnt) ? g_src[start + j0 + lane] : 0;
        int jj = 0;
        for (; jj + 8 <= cnt; jj += 8) {
            int sA = __shfl_sync(0xFFFFFFFFu, src, jj + grp);
            int sB = __shfl_sync(0xFFFFFFFFu, src, jj + 4 + grp);
            uint4 ra = *(const uint4*)&g_h1s[sA * 64 + sub * 8];
            uint4 rb = *(const uint4*)&g_h1s[sB * 64 + sub * 8];
            __half2* ha = (__half2*)&ra;
            __half2* hb = (__half2*)&rb;
            acc[0] = __hadd2(acc[0], ha[0]);
            acc[1] = __hadd2(acc[1], ha[1]);
            acc[2] = __hadd2(acc[2], ha[2]);
            acc[3] = __hadd2(acc[3], ha[3]);
            acc[0] = __hadd2(acc[0], hb[0]);
            acc[1] = __hadd2(acc[1], hb[1]);
            acc[2] = __hadd2(acc[2], hb[2]);
            acc[3] = __hadd2(acc[3], hb[3]);
        }
        for (; jj < cnt; jj += 4) {
            int sidx = jj + grp;
            int s = __shfl_sync(0xFFFFFFFFu, src, sidx < cnt ? sidx : 0);
            if (sidx < cnt) {
                uint4 raw = *(const uint4*)&g_h1s[s * 64 + sub * 8];
                __half2* hp = (__half2*)&raw;
                acc[0] = __hadd2(acc[0], hp[0]);
                acc[1] = __hadd2(acc[1], hp[1]);
                acc[2] = __hadd2(acc[2], hp[2]);
                acc[3] = __hadd2(acc[3], hp[3]);
            }
        }
    }

    // Reduce the 4 lane-groups (lanes l, l^8, l^16).
#pragma unroll
    for (int o = 8; o <= 16; o <<= 1) {
#pragma unroll
        for (int p = 0; p < 4; p++) {
            unsigned u = __shfl_xor_sync(0xFFFFFFFFu,
                                         *(unsigned*)&acc[p], o);
            acc[p] = __hadd2(acc[p], *(__half2*)&u);
        }
    }

    if (lane < 8)
        *(uint4*)&g_agg1[gw * 64 + lane * 8] = *(uint4*)acc;   // 128B row
}

// ---------------------------------------------------------------------------
// GEMM2: a = relu(agg1*dinv + b1);  h2s = fp16((a @ W2) * dinv)
// ---------------------------------------------------------------------------
__global__ void __launch_bounds__(128) k_gemm2(const float* __restrict__ W2,
                                               const float* __restrict__ b1, int n) {
    __shared__ __align__(16) float xs[64][132];
    __shared__ __align__(16) float ws[64][32];

    int t = threadIdx.x;
    int rowbase = blockIdx.x * 128;

    const float4* W4 = (const float4*)W2;
    float4* ws4 = (float4*)ws;
#pragma unroll
    for (int i = t; i < 512; i += 128) ws4[i] = W4[i];

    const uint2* a2 = (const uint2*)g_agg1;
    const float4* b14 = (const float4*)b1;
#pragma unroll
    for (int i = t; i < 2048; i += 128) {
        int r = i >> 4, c4 = i & 15;
        int gr = rowbase + r;
        float4 v = make_float4(0.f, 0.f, 0.f, 0.f);
        if (gr < n) {
            uint2 raw = a2[gr * 16 + c4];
            float2 u01 = __half22float2(*(__half2*)&raw.x);
            float2 u23 = __half22float2(*(__half2*)&raw.y);
            float s = g_dinv[gr];
            float4 bb = b14[c4];
            v.x = fmaxf(fmaf(u01.x, s, bb.x), 0.f);
            v.y = fmaxf(fmaf(u01.y, s, bb.y), 0.f);
            v.z = fmaxf(fmaf(u23.x, s, bb.z), 0.f);
            v.w = fmaxf(fmaf(u23.y, s, bb.w), 0.f);
        }
        xs[c4 * 4 + 0][r] = v.x;
        xs[c4 * 4 + 1][r] = v.y;
        xs[c4 * 4 + 2][r] = v.z;
        xs[c4 * 4 + 3][r] = v.w;
    }
    __syncthreads();

    int tx = t & 7;
    int ty = t >> 3;
    float acc[8][4];
#pragma unroll
    for (int a = 0; a < 8; a++)
#pragma unroll
        for (int b = 0; b < 4; b++) acc[a][b] = 0.f;

#pragma unroll 8
    for (int k = 0; k < 64; k++) {
        float4 xa = *(const float4*)&xs[k][ty * 8];
        float4 xb = *(const float4*)&xs[k][ty * 8 + 4];
        float4 w0 = *(const float4*)&ws[k][tx * 4];
        float xv[8] = {xa.x, xa.y, xa.z, xa.w, xb.x, xb.y, xb.z, xb.w};
#pragma unroll
        for (int rr = 0; rr < 8; rr++) {
            acc[rr][0] += xv[rr] * w0.x; acc[rr][1] += xv[rr] * w0.y;
            acc[rr][2] += xv[rr] * w0.z; acc[rr][3] += xv[rr] * w0.w;
        }
    }

#pragma unroll
    for (int rr = 0; rr < 8; rr++) {
        int gr = rowbase + ty * 8 + rr;
        if (gr >= n) break;
        float s = g_dinv[gr];
        __half2 o[2];
        o[0] = __floats2half2_rn(acc[rr][0] * s, acc[rr][1] * s);
        o[1] = __floats2half2_rn(acc[rr][2] * s, acc[rr][3] * s);
        *(uint2*)&g_h2s[gr * 32 + tx * 4] = *(uint2*)o;
    }
}

// ---------------------------------------------------------------------------
// Aggregation layer 2 + log_softmax. 64B rows: grp=lane>>2 (8 rows/step),
// sub=lane&3. Inner loop unrolled x2: 16 sources in flight per iteration.
// ---------------------------------------------------------------------------
__global__ void k_agg2_lsm(const float* __restrict__ b2, float* __restrict__ out, int n) {
    __shared__ __align__(16) __half s_red[8][32];   // 8 warps x 32 cols

    int warp = threadIdx.x >> 5;
    int gw = (blockIdx.x * blockDim.x + threadIdx.x) >> 5;
    int lane = threadIdx.x & 31;
    if (gw >= n) return;

    int grp = lane >> 2;    // 0..7
    int sub = lane & 3;     // 0..3: cols sub*8..+7

    __half2 acc[4];
    if (grp == 0) {
        uint4 raw = *(const uint4*)&g_h2s[gw * 32 + sub * 8];
        __half2* hp = (__half2*)&raw;
        acc[0] = hp[0]; acc[1] = hp[1]; acc[2] = hp[2]; acc[3] = hp[3];
    } else {
        __half2 z = __floats2half2_rn(0.f, 0.f);
        acc[0] = z; acc[1] = z; acc[2] = z; acc[3] = z;
    }

    int start = g_rowstart[gw];
    int deg = g_deg[gw];

    for (int j0 = 0; j0 < deg; j0 += 32) {
        int cnt = min(32, deg - j0);
        int src = (lane < cnt) ? g_src[start + j0 + lane] : 0;
        int jj = 0;
        for (; jj + 16 <= cnt; jj += 16) {
            int sA = __shfl_sync(0xFFFFFFFFu, src, jj + grp);
            int sB = __shfl_sync(0xFFFFFFFFu, src, jj + 8 + grp);
            uint4 ra = *(const uint4*)&g_h2s[sA * 32 + sub * 8];
            uint4 rb = *(const uint4*)&g_h2s[sB * 32 + sub * 8];
            __half2* ha = (__half2*)&ra;
            __half2* hb = (__half2*)&rb;
            acc[0] = __hadd2(acc[0], ha[0]);
            acc[1] = __hadd2(acc[1], ha[1]);
            acc[2] = __hadd2(acc[2], ha[2]);
            acc[3] = __hadd2(acc[3], ha[3]);
            acc[0] = __hadd2(acc[0], hb[0]);
            acc[1] = __hadd2(acc[1], hb[1]);
            acc[2] = __hadd2(acc[2], hb[2]);
            acc[3] = __hadd2(acc[3], hb[3]);
        }
        for (; jj < cnt; jj += 8) {
            int sidx = jj + grp;
            int s = __shfl_sync(0xFFFFFFFFu, src, sidx < cnt ? sidx : 0);
            if (sidx < cnt) {
                uint4 raw = *(const uint4*)&g_h2s[s * 32 + sub * 8];
                __half2* hp = (__half2*)&raw;
                acc[0] = __hadd2(acc[0], hp[0]);
                acc[1] = __hadd2(acc[1], hp[1]);
                acc[2] = __hadd2(acc[2], hp[2]);
                acc[3] = __hadd2(acc[3], hp[3]);
            }
        }
    }

    // Reduce the 8 lane-groups (xor 4, 8, 16).
#pragma unroll
    for (int o = 4; o <= 16; o <<= 1) {
#pragma unroll
        for (int p = 0; p < 4; p++) {
            unsigned u = __shfl_xor_sync(0xFFFFFFFFu,
                                         *(unsigned*)&acc[p], o);
            acc[p] = __hadd2(acc[p], *(__half2*)&u);
        }
    }

    if (lane < 4)
        *(uint4*)&s_red[warp][lane * 8] = *(uint4*)acc;
    __syncwarp();

    float z = fmaf(__half2float(s_red[warp][lane]), g_dinv[gw], b2[lane]);
    float m = z;
#pragma unroll
    for (int o = 16; o; o >>= 1) m = fmaxf(m, __shfl_xor_sync(0xFFFFFFFFu, m, o));
    float ex = expf(z - m);
    float s = ex;
#pragma unroll
    for (int o = 16; o; o >>= 1) s += __shfl_xor_sync(0xFFFFFFFFu, s, o);
    out[gw * 32 + lane] = z - m - logf(s);
}

// ---------------------------------------------------------------------------
extern "C" void kernel_launch(void* const* d_in, const int* in_sizes, int n_in,
                              void* d_out, int out_size) {
    const float* x  = (const float*)d_in[0];
    const int*   ei = (const int*)d_in[1];
    const float* W1 = (const float*)d_in[2];
    const float* b1 = (const float*)d_in[3];
    const float* W2 = (const float*)d_in[4];
    const float* b2 = (const float*)d_in[5];
    float* out = (float*)d_out;

    int n = in_sizes[0] / 64;   // 100000
    int e = in_sizes[1] / 2;    // 1600000
    const int* row = ei;        // sources
    const int* col = ei + e;    // targets

    cudaFuncSetAttribute(k_gemm1_count, cudaFuncAttributeMaxDynamicSharedMemorySize,
                         GEMM1_SMEM_BYTES);

    void* degp = nullptr;
    cudaGetSymbolAddress(&degp, g_deg);
    cudaMemsetAsync(degp, 0, (NMAX + 1) * sizeof(int));

    int gemmBlocks = (n + 127) / 128;
    int cntBlocks = (e + CNT_EDGES_PER_BLOCK - 1) / CNT_EDGES_PER_BLOCK;
    k_gemm1_count<<<gemmBlocks + cntBlocks, 128, GEMM1_SMEM_BYTES>>>(x, W1, col, n, e, gemmBlocks);

    int nb = (n + SCAN_CHUNK - 1) / SCAN_CHUNK;   // 196
    k_scan<<<nb, 256>>>(n);
    k_fill<<<(e + 1023) / 1024, 256>>>(row, col, e);

    k_agg1<<<(n + 7) / 8, 256>>>(n);

    k_gemm2<<<(n + 127) / 128, 128>>>(W2, b1, n);
    k_agg2_lsm<<<(n + 7) / 8, 256>>>(b2, out, n);
}

// round 13
// speedup vs baseline: 1.6569x; 1.0286x over previous
#include <cuda_runtime.h>
#include <cuda_fp16.h>
#include <cstdint>

#define NMAX 100000
#define EMAX 1600000
#define SCAN_CHUNK 512
#define CNT_EDGES_PER_BLOCK 2048

__device__ int    g_deg[NMAX + 1];
__device__ float  g_dinv[NMAX];
__device__ int    g_rowstart[NMAX];
__device__ int    g_cursor[NMAX];
__device__ int    g_src[EMAX];
__device__ __half g_h1s[NMAX * 64];
__device__ __half g_agg1[NMAX * 64];
__device__ __half g_h2s[NMAX * 32];

__device__ __forceinline__ void ldsm_a(uint32_t* r, uint32_t addr) {
    asm volatile("ldmatrix.sync.aligned.m8n8.x4.shared.b16 {%0,%1,%2,%3}, [%4];"
                 : "=r"(r[0]), "=r"(r[1]), "=r"(r[2]), "=r"(r[3]) : "r"(addr));
}

__device__ __forceinline__ void ldsm_bt(uint32_t* r, uint32_t addr) {
    asm volatile("ldmatrix.sync.aligned.m8n8.x4.trans.shared.b16 {%0,%1,%2,%3}, [%4];"
                 : "=r"(r[0]), "=r"(r[1]), "=r"(r[2]), "=r"(r[3]) : "r"(addr));
}

__device__ __forceinline__ void mma16816(float* d, const uint32_t* a, uint32_t b0, uint32_t b1) {
    asm volatile("mma.sync.aligned.m16n8k16.row.col.f32.f16.f16.f32 "
                 "{%0,%1,%2,%3}, {%4,%5,%6,%7}, {%8,%9}, {%0,%1,%2,%3};"
                 : "+f"(d[0]), "+f"(d[1]), "+f"(d[2]), "+f"(d[3])
                 : "r"(a[0]), "r"(a[1]), "r"(a[2]), "r"(a[3]), "r"(b0), "r"(b1));
}

__device__ __forceinline__ __half2 f2h(float lo, float hi) {
    return __floats2half2_rn(lo, hi);
}

// ---------------------------------------------------------------------------
// K1: blocks < gemmBlocks run tensor-core GEMM1 (h1raw = x@W1, fp16 out);
//     blocks >= gemmBlocks count in-degrees.
// ---------------------------------------------------------------------------
__global__ void __launch_bounds__(256) k_gemm1_count(const float* __restrict__ x,
                                                     const float* __restrict__ W,
                                                     const int* __restrict__ col,
                                                     int n, int e, int gemmBlocks) {
    if ((int)blockIdx.x >= gemmBlocks) {
        int b = blockIdx.x - gemmBlocks;
        int base = b * CNT_EDGES_PER_BLOCK + threadIdx.x;
#pragma unroll
        for (int j = 0; j < 8; j++) {
            int idx = base + j * 256;
            if (idx < e) atomicAdd(&g_deg[__ldg(&col[idx])], 1);
        }
        return;
    }

    __shared__ __align__(16) __half As[128][72];   // 144B stride
    __shared__ __align__(16) __half Bs[64][72];

    int t = threadIdx.x;
    int rowbase = blockIdx.x * 128;

    const float4* W4 = (const float4*)W;
    for (int i = t; i < 1024; i += 256) {
        int k = i >> 4;
        int c4 = i & 15;
        float4 v = W4[i];
        __half2 p0 = f2h(v.x, v.y);
        __half2 p1 = f2h(v.z, v.w);
        uint2 u;
        u.x = *(uint32_t*)&p0;
        u.y = *(uint32_t*)&p1;
        *(uint2*)&Bs[k][c4 * 4] = u;
    }

    const float4* x4 = (const float4*)x;
    for (int i = t; i < 2048; i += 256) {
        int r = i >> 4;
        int c4 = i & 15;
        int gr = rowbase + r;
        float4 v = make_float4(0.f, 0.f, 0.f, 0.f);
        if (gr < n) v = x4[gr * 16 + c4];
        __half2 p0 = f2h(v.x, v.y);
        __half2 p1 = f2h(v.z, v.w);
        uint2 u;
        u.x = *(uint32_t*)&p0;
        u.y = *(uint32_t*)&p1;
        *(uint2*)&As[r][c4 * 4] = u;
    }
    __syncthreads();

    int warp = t >> 5;
    int lane = t & 31;
    int m0 = warp * 16;

    float d[8][4];
#pragma unroll
    for (int nt = 0; nt < 8; nt++) {
        d[nt][0] = 0.f; d[nt][1] = 0.f; d[nt][2] = 0.f; d[nt][3] = 0.f;
    }

#pragma unroll
    for (int k0 = 0; k0 < 64; k0 += 16) {
        uint32_t afr[4];
        uint32_t aaddr = (uint32_t)__cvta_generic_to_shared(
            &As[m0 + (lane & 15)][k0 + (lane >> 4) * 8]);
        ldsm_a(afr, aaddr);
#pragma unroll
        for (int nn = 0; nn < 4; nn++) {
            uint32_t bfr[4];
            uint32_t baddr = (uint32_t)__cvta_generic_to_shared(
                &Bs[k0 + (lane & 15)][nn * 16 + (lane >> 4) * 8]);
            ldsm_bt(bfr, baddr);
            mma16816(d[nn * 2], afr, bfr[0], bfr[1]);
            mma16816(d[nn * 2 + 1], afr, bfr[2], bfr[3]);
        }
    }

    int r0 = rowbase + m0 + (lane >> 2);
    int cbase = (lane & 3) * 2;
#pragma unroll
    for (int nt = 0; nt < 8; nt++) {
        int colx = nt * 8 + cbase;
        __half2 h0 = f2h(d[nt][0], d[nt][1]);
        __half2 h1 = f2h(d[nt][2], d[nt][3]);
        if (r0 < n) *(__half2*)&g_h1s[r0 * 64 + colx] = h0;
        if (r0 + 8 < n) *(__half2*)&g_h1s[(r0 + 8) * 64 + colx] = h1;
    }
}

// ---------------------------------------------------------------------------
// Fused scan + dinv + in-place h1s dinv scaling.
// ---------------------------------------------------------------------------
__global__ void k_scan(int n) {
    __shared__ int s_warp[8];
    __shared__ int s_base;
    __shared__ float s_dinv[SCAN_CHUNK];
    int t = threadIdx.x;
    int base = blockIdx.x * SCAN_CHUNK;
    int i0 = base + 2 * t;
    int a = (i0 < n) ? g_deg[i0] : 0;
    int c = (i0 + 1 < n) ? g_deg[i0 + 1] : 0;
    float da = rsqrtf((float)(a + 1));
    float dc = rsqrtf((float)(c + 1));
    s_dinv[2 * t] = da;
    s_dinv[2 * t + 1] = dc;
    if (i0 < n) g_dinv[i0] = da;
    if (i0 + 1 < n) g_dinv[i0 + 1] = dc;

    int sum2 = a + c;
    int lane = t & 31;
    int wid = t >> 5;
    int v = sum2;
#pragma unroll
    for (int o = 1; o < 32; o <<= 1) {
        int u = __shfl_up_sync(0xFFFFFFFFu, v, o);
        if (lane >= o) v += u;
    }
    if (lane == 31) s_warp[wid] = v;
    __syncthreads();
    if (t < 8) {
        int w = s_warp[t];
#pragma unroll
        for (int o = 1; o < 8; o <<= 1) {
            int u = __shfl_up_sync(0xFFu, w, o);
            if (t >= o) w += u;
        }
        s_warp[t] = w;
    }
    __syncthreads();
    int woff = wid ? s_warp[wid - 1] : 0;
    int incl = v + woff;
    if (t == 255) s_base = atomicAdd(&g_deg[NMAX], incl);
    __syncthreads();
    int excl = incl - sum2 + s_base;
    if (i0 < n) { g_rowstart[i0] = excl; g_cursor[i0] = excl; }
    if (i0 + 1 < n) { g_rowstart[i0 + 1] = excl + a; g_cursor[i0 + 1] = excl + a; }

    for (int i = t; i < 4096; i += 256) {
        int rl = i >> 3;
        int c8 = i & 7;
        int node = base + rl;
        if (node >= n) break;
        float s = s_dinv[rl];
        uint4 raw = *(const uint4*)&g_h1s[node * 64 + c8 * 8];
        __half2* hp = (__half2*)&raw;
        __half2 o[4];
#pragma unroll
        for (int p = 0; p < 4; p++) {
            float2 f = __half22float2(hp[p]);
            o[p] = f2h(f.x * s, f.y * s);
        }
        *(uint4*)&g_h1s[node * 64 + c8 * 8] = *(uint4*)o;
    }
}

// ---------------------------------------------------------------------------
// CSR fill: 4 edges per thread, independent atomics/stores (MLP=4).
// ---------------------------------------------------------------------------
__global__ void k_fill(const int* __restrict__ row, const int* __restrict__ col, int e) {
    int base = blockIdx.x * 1024 + threadIdx.x;
    int idx[4];
    int pos[4];
    int rv[4];
#pragma unroll
    for (int j = 0; j < 4; j++) {
        int i = base + j * 256;
        idx[j] = i;
        if (i < e) {
            int c = col[i];
            pos[j] = atomicAdd(&g_cursor[c], 1);
            rv[j] = row[i];
        }
    }
#pragma unroll
    for (int j = 0; j < 4; j++) {
        if (idx[j] < e) g_src[pos[j]] = rv[j];
    }
}

// ---------------------------------------------------------------------------
// Aggregation layer 1: LDG.128 lane-group gather, fp16 HADD2 accumulate.
// grp=lane>>3 (4 rows per load batch), sub=lane&7 (16B chunk).
// Main loop: 16 sources per iteration (4 independent LDG.128 per lane).
// ---------------------------------------------------------------------------
__global__ void k_agg1(int n) {
    int gw = (blockIdx.x * blockDim.x + threadIdx.x) >> 5;
    int lane = threadIdx.x & 31;
    if (gw >= n) return;

    int grp = lane >> 3;
    int sub = lane & 7;

    __half2 acc[4];
    if (grp == 0) {
        uint4 raw = *(const uint4*)&g_h1s[gw * 64 + sub * 8];
        __half2* hp = (__half2*)&raw;
        acc[0] = hp[0]; acc[1] = hp[1]; acc[2] = hp[2]; acc[3] = hp[3];
    } else {
        __half2 z = f2h(0.f, 0.f);
        acc[0] = z; acc[1] = z; acc[2] = z; acc[3] = z;
    }

    int start = g_rowstart[gw];
    int deg = g_deg[gw];

    for (int j0 = 0; j0 < deg; j0 += 32) {
        int cnt = min(32, deg - j0);
        int src = (lane < cnt) ? g_src[start + j0 + lane] : 0;
        int jj = 0;
        for (; jj + 16 <= cnt; jj += 16) {
            int s0 = __shfl_sync(0xFFFFFFFFu, src, jj + grp);
            int s1 = __shfl_sync(0xFFFFFFFFu, src, jj + 4 + grp);
            int s2 = __shfl_sync(0xFFFFFFFFu, src, jj + 8 + grp);
            int s3 = __shfl_sync(0xFFFFFFFFu, src, jj + 12 + grp);
            uint4 r0 = *(const uint4*)&g_h1s[s0 * 64 + sub * 8];
            uint4 r1 = *(const uint4*)&g_h1s[s1 * 64 + sub * 8];
            uint4 r2 = *(const uint4*)&g_h1s[s2 * 64 + sub * 8];
            uint4 r3 = *(const uint4*)&g_h1s[s3 * 64 + sub * 8];
            __half2* h0 = (__half2*)&r0;
            __half2* h1 = (__half2*)&r1;
            __half2* h2 = (__half2*)&r2;
            __half2* h3 = (__half2*)&r3;
#pragma unroll
            for (int p = 0; p < 4; p++) {
                acc[p] = __hadd2(acc[p], h0[p]);
                acc[p] = __hadd2(acc[p], h1[p]);
                acc[p] = __hadd2(acc[p], h2[p]);
                acc[p] = __hadd2(acc[p], h3[p]);
            }
        }
        for (; jj + 8 <= cnt; jj += 8) {
            int sA = __shfl_sync(0xFFFFFFFFu, src, jj + grp);
            int sB = __shfl_sync(0xFFFFFFFFu, src, jj + 4 + grp);
            uint4 ra = *(const uint4*)&g_h1s[sA * 64 + sub * 8];
            uint4 rb = *(const uint4*)&g_h1s[sB * 64 + sub * 8];
            __half2* ha = (__half2*)&ra;
            __half2* hb = (__half2*)&rb;
#pragma unroll
            for (int p = 0; p < 4; p++) {
                acc[p] = __hadd2(acc[p], ha[p]);
                acc[p] = __hadd2(acc[p], hb[p]);
            }
        }
        for (; jj < cnt; jj += 4) {
            int sidx = jj + grp;
            int s = __shfl_sync(0xFFFFFFFFu, src, (sidx < cnt) ? sidx : 0);
            if (sidx < cnt) {
                uint4 raw = *(const uint4*)&g_h1s[s * 64 + sub * 8];
                __half2* hp = (__half2*)&raw;
#pragma unroll
                for (int p = 0; p < 4; p++) {
                    acc[p] = __hadd2(acc[p], hp[p]);
                }
            }
        }
    }

#pragma unroll
    for (int o = 8; o <= 16; o <<= 1) {
#pragma unroll
        for (int p = 0; p < 4; p++) {
            unsigned u = __shfl_xor_sync(0xFFFFFFFFu, *(unsigned*)&acc[p], o);
            acc[p] = __hadd2(acc[p], *(__half2*)&u);
        }
    }

    if (lane < 8) {
        *(uint4*)&g_agg1[gw * 64 + lane * 8] = *(uint4*)acc;
    }
}

// ---------------------------------------------------------------------------
// GEMM2: a = relu(agg1*dinv + b1);  h2s = fp16((a @ W2) * dinv)
// ---------------------------------------------------------------------------
__global__ void __launch_bounds__(128) k_gemm2(const float* __restrict__ W2,
                                               const float* __restrict__ b1, int n) {
    __shared__ __align__(16) float xs[64][132];
    __shared__ __align__(16) float ws[64][32];

    int t = threadIdx.x;
    int rowbase = blockIdx.x * 128;

    const float4* W4 = (const float4*)W2;
    float4* ws4 = (float4*)ws;
    for (int i = t; i < 512; i += 128) ws4[i] = W4[i];

    const uint2* a2 = (const uint2*)g_agg1;
    const float4* b14 = (const float4*)b1;
    for (int i = t; i < 2048; i += 128) {
        int r = i >> 4;
        int c4 = i & 15;
        int gr = rowbase + r;
        float4 v = make_float4(0.f, 0.f, 0.f, 0.f);
        if (gr < n) {
            uint2 raw = a2[gr * 16 + c4];
            float2 u01 = __half22float2(*(__half2*)&raw.x);
            float2 u23 = __half22float2(*(__half2*)&raw.y);
            float s = g_dinv[gr];
            float4 bb = b14[c4];
            v.x = fmaxf(fmaf(u01.x, s, bb.x), 0.f);
            v.y = fmaxf(fmaf(u01.y, s, bb.y), 0.f);
            v.z = fmaxf(fmaf(u23.x, s, bb.z), 0.f);
            v.w = fmaxf(fmaf(u23.y, s, bb.w), 0.f);
        }
        xs[c4 * 4 + 0][r] = v.x;
        xs[c4 * 4 + 1][r] = v.y;
        xs[c4 * 4 + 2][r] = v.z;
        xs[c4 * 4 + 3][r] = v.w;
    }
    __syncthreads();

    int tx = t & 7;
    int ty = t >> 3;
    float acc[8][4];
#pragma unroll
    for (int i = 0; i < 8; i++) {
        acc[i][0] = 0.f; acc[i][1] = 0.f; acc[i][2] = 0.f; acc[i][3] = 0.f;
    }

#pragma unroll 8
    for (int k = 0; k < 64; k++) {
        float4 xa = *(const float4*)&xs[k][ty * 8];
        float4 xb = *(const float4*)&xs[k][ty * 8 + 4];
        float4 w0 = *(const float4*)&ws[k][tx * 4];
        float xv[8];
        xv[0] = xa.x; xv[1] = xa.y; xv[2] = xa.z; xv[3] = xa.w;
        xv[4] = xb.x; xv[5] = xb.y; xv[6] = xb.z; xv[7] = xb.w;
#pragma unroll
        for (int rr = 0; rr < 8; rr++) {
            acc[rr][0] += xv[rr] * w0.x;
            acc[rr][1] += xv[rr] * w0.y;
            acc[rr][2] += xv[rr] * w0.z;
            acc[rr][3] += xv[rr] * w0.w;
        }
    }

#pragma unroll
    for (int rr = 0; rr < 8; rr++) {
        int gr = rowbase + ty * 8 + rr;
        if (gr >= n) break;
        float s = g_dinv[gr];
        __half2 o[2];
        o[0] = f2h(acc[rr][0] * s, acc[rr][1] * s);
        o[1] = f2h(acc[rr][2] * s, acc[rr][3] * s);
        *(uint2*)&g_h2s[gr * 32 + tx * 4] = *(uint2*)o;
    }
}

// ---------------------------------------------------------------------------
// Aggregation layer 2 + log_softmax. 64B rows: grp=lane>>2 (8 rows/step),
// sub=lane&3. Unrolled x2 (16 sources in flight).
// ---------------------------------------------------------------------------
__global__ void k_agg2_lsm(const float* __restrict__ b2, float* __restrict__ out, int n) {
    __shared__ __align__(16) __half s_red[8][32];

    int warp = threadIdx.x >> 5;
    int gw = (blockIdx.x * blockDim.x + threadIdx.x) >> 5;
    int lane = threadIdx.x & 31;
    if (gw >= n) return;

    int grp = lane >> 2;
    int sub = lane & 3;

    __half2 acc[4];
    if (grp == 0) {
        uint4 raw = *(const uint4*)&g_h2s[gw * 32 + sub * 8];
        __half2* hp = (__half2*)&raw;
        acc[0] = hp[0]; acc[1] = hp[1]; acc[2] = hp[2]; acc[3] = hp[3];
    } else {
        __half2 z = f2h(0.f, 0.f);
        acc[0] = z; acc[1] = z; acc[2] = z; acc[3] = z;
    }

    int start = g_rowstart[gw];
    int deg = g_deg[gw];

    for (int j0 = 0; j0 < deg; j0 += 32) {
        int cnt = min(32, deg - j0);
        int src = (lane < cnt) ? g_src[start + j0 + lane] : 0;
        int jj = 0;
        for (; jj + 16 <= cnt; jj += 16) {
            int sA = __shfl_sync(0xFFFFFFFFu, src, jj + grp);
            int sB = __shfl_sync(0xFFFFFFFFu, src, jj + 8 + grp);
            uint4 ra = *(const uint4*)&g_h2s[sA * 32 + sub * 8];
            uint4 rb = *(const uint4*)&g_h2s[sB * 32 + sub * 8];
            __half2* ha = (__half2*)&ra;
            __half2* hb = (__half2*)&rb;
#pragma unroll
            for (int p = 0; p < 4; p++) {
                acc[p] = __hadd2(acc[p], ha[p]);
                acc[p] = __hadd2(acc[p], hb[p]);
            }
        }
        for (; jj < cnt; jj += 8) {
            int sidx = jj + grp;
            int s = __shfl_sync(0xFFFFFFFFu, src, (sidx < cnt) ? sidx : 0);
            if (sidx < cnt) {
                uint4 raw = *(const uint4*)&g_h2s[s * 32 + sub * 8];
                __half2* hp = (__half2*)&raw;
#pragma unroll
                for (int p = 0; p < 4; p++) {
                    acc[p] = __hadd2(acc[p], hp[p]);
                }
            }
        }
    }

#pragma unroll
    for (int o = 4; o <= 16; o <<= 1) {
#pragma unroll
        for (int p = 0; p < 4; p++) {
            unsigned u = __shfl_xor_sync(0xFFFFFFFFu, *(unsigned*)&acc[p], o);
            acc[p] = __hadd2(acc[p], *(__half2*)&u);
        }
    }

    if (lane < 4) {
        *(uint4*)&s_red[warp][lane * 8] = *(uint4*)acc;
    }
    __syncwarp();

    float z = fmaf(__half2float(s_red[warp][lane]), g_dinv[gw], b2[lane]);
    float m = z;
#pragma unroll
    for (int o = 16; o; o >>= 1) m = fmaxf(m, __shfl_xor_sync(0xFFFFFFFFu, m, o));
    float ex = expf(z - m);
    float s = ex;
#pragma unroll
    for (int o = 16; o; o >>= 1) s += __shfl_xor_sync(0xFFFFFFFFu, s, o);
    out[gw * 32 + lane] = z - m - logf(s);
}

// ---------------------------------------------------------------------------
extern "C" void kernel_launch(void* const* d_in, const int* in_sizes, int n_in,
                              void* d_out, int out_size) {
    const float* x = (const float*)d_in[0];
    const int* ei = (const int*)d_in[1];
    const float* W1 = (const float*)d_in[2];
    const float* b1 = (const float*)d_in[3];
    const float* W2 = (const float*)d_in[4];
    const float* b2 = (const float*)d_in[5];
    float* out = (float*)d_out;

    int n = in_sizes[0] / 64;
    int e = in_sizes[1] / 2;
    const int* row = ei;
    const int* col = ei + e;

    void* degp = 0;
    cudaGetSymbolAddress(&degp, g_deg);
    cudaMemsetAsync(degp, 0, (NMAX + 1) * sizeof(int));

    int gemmBlocks = (n + 127) / 128;
    int cntBlocks = (e + CNT_EDGES_PER_BLOCK - 1) / CNT_EDGES_PER_BLOCK;
    k_gemm1_count<<<gemmBlocks + cntBlocks, 256>>>(x, W1, col, n, e, gemmBlocks);

    int nb = (n + SCAN_CHUNK - 1) / SCAN_CHUNK;
    k_scan<<<nb, 256>>>(n);
    k_fill<<<(e + 1023) / 1024, 256>>>(row, col, e);

    k_agg1<<<(n + 7) / 8, 256>>>(n);

    k_gemm2<<<(n + 127) / 128, 128>>>(W2, b1, n);
    k_agg2_lsm<<<(n + 7) / 8, 256>>>(b2, out, n);
}

// round 15
// speedup vs baseline: 1.9627x; 1.1846x over previous
#include <cuda_runtime.h>
#include <cuda_fp16.h>
#include <cstdint>

#define NMAX 100000
#define EMAX 1600000
#define SCAN_CHUNK 512
#define CNT_EDGES_PER_BLOCK 2048

__device__ int    g_deg[NMAX + 1];
__device__ float  g_dinv[NMAX];
__device__ int    g_rowstart[NMAX];
__device__ int    g_cursor[NMAX];
__device__ int    g_src[EMAX];
__device__ __half g_h1s[NMAX * 64];
__device__ __half g_agg1[NMAX * 64];
__device__ __half g_h2s[NMAX * 32];

__device__ __forceinline__ void ldsm_a(uint32_t* r, uint32_t addr) {
    asm volatile("ldmatrix.sync.aligned.m8n8.x4.shared.b16 {%0,%1,%2,%3}, [%4];"
                 : "=r"(r[0]), "=r"(r[1]), "=r"(r[2]), "=r"(r[3]) : "r"(addr));
}

__device__ __forceinline__ void ldsm_bt(uint32_t* r, uint32_t addr) {
    asm volatile("ldmatrix.sync.aligned.m8n8.x4.trans.shared.b16 {%0,%1,%2,%3}, [%4];"
                 : "=r"(r[0]), "=r"(r[1]), "=r"(r[2]), "=r"(r[3]) : "r"(addr));
}

__device__ __forceinline__ void mma16816(float* d, const uint32_t* a, uint32_t b0, uint32_t b1) {
    asm volatile("mma.sync.aligned.m16n8k16.row.col.f32.f16.f16.f32 "
                 "{%0,%1,%2,%3}, {%4,%5,%6,%7}, {%8,%9}, {%0,%1,%2,%3};"
                 : "+f"(d[0]), "+f"(d[1]), "+f"(d[2]), "+f"(d[3])
                 : "r"(a[0]), "r"(a[1]), "r"(a[2]), "r"(a[3]), "r"(b0), "r"(b1));
}

__device__ __forceinline__ __half2 f2h(float lo, float hi) {
    return __floats2half2_rn(lo, hi);
}

// ---------------------------------------------------------------------------
// K1: blocks < gemmBlocks run tensor-core GEMM1 (h1raw = x@W1, fp16 out);
//     blocks >= gemmBlocks count in-degrees.
// ---------------------------------------------------------------------------
__global__ void __launch_bounds__(256) k_gemm1_count(const float* __restrict__ x,
                                                     const float* __restrict__ W,
                                                     const int* __restrict__ col,
                                                     int n, int e, int gemmBlocks) {
    if ((int)blockIdx.x >= gemmBlocks) {
        int b = blockIdx.x - gemmBlocks;
        int base = b * CNT_EDGES_PER_BLOCK + threadIdx.x;
#pragma unroll
        for (int j = 0; j < 8; j++) {
            int idx = base + j * 256;
            if (idx < e) atomicAdd(&g_deg[__ldg(&col[idx])], 1);
        }
        return;
    }

    __shared__ __align__(16) __half As[128][72];   // 144B stride
    __shared__ __align__(16) __half Bs[64][72];

    int t = threadIdx.x;
    int rowbase = blockIdx.x * 128;

    const float4* W4 = (const float4*)W;
    for (int i = t; i < 1024; i += 256) {
        int k = i >> 4;
        int c4 = i & 15;
        float4 v = W4[i];
        __half2 p0 = f2h(v.x, v.y);
        __half2 p1 = f2h(v.z, v.w);
        uint2 u;
        u.x = *(uint32_t*)&p0;
        u.y = *(uint32_t*)&p1;
        *(uint2*)&Bs[k][c4 * 4] = u;
    }

    const float4* x4 = (const float4*)x;
    for (int i = t; i < 2048; i += 256) {
        int r = i >> 4;
        int c4 = i & 15;
        int gr = rowbase + r;
        float4 v = make_float4(0.f, 0.f, 0.f, 0.f);
        if (gr < n) v = x4[gr * 16 + c4];
        __half2 p0 = f2h(v.x, v.y);
        __half2 p1 = f2h(v.z, v.w);
        uint2 u;
        u.x = *(uint32_t*)&p0;
        u.y = *(uint32_t*)&p1;
        *(uint2*)&As[r][c4 * 4] = u;
    }
    __syncthreads();

    int warp = t >> 5;
    int lane = t & 31;
    int m0 = warp * 16;

    float d[8][4];
#pragma unroll
    for (int nt = 0; nt < 8; nt++) {
        d[nt][0] = 0.f; d[nt][1] = 0.f; d[nt][2] = 0.f; d[nt][3] = 0.f;
    }

#pragma unroll
    for (int k0 = 0; k0 < 64; k0 += 16) {
        uint32_t afr[4];
        uint32_t aaddr = (uint32_t)__cvta_generic_to_shared(
            &As[m0 + (lane & 15)][k0 + (lane >> 4) * 8]);
        ldsm_a(afr, aaddr);
#pragma unroll
        for (int nn = 0; nn < 4; nn++) {
            uint32_t bfr[4];
            uint32_t baddr = (uint32_t)__cvta_generic_to_shared(
                &Bs[k0 + (lane & 15)][nn * 16 + (lane >> 4) * 8]);
            ldsm_bt(bfr, baddr);
            mma16816(d[nn * 2], afr, bfr[0], bfr[1]);
            mma16816(d[nn * 2 + 1], afr, bfr[2], bfr[3]);
        }
    }

    int r0 = rowbase + m0 + (lane >> 2);
    int cbase = (lane & 3) * 2;
#pragma unroll
    for (int nt = 0; nt < 8; nt++) {
        int colx = nt * 8 + cbase;
        __half2 h0 = f2h(d[nt][0], d[nt][1]);
        __half2 h1 = f2h(d[nt][2], d[nt][3]);
        if (r0 < n) *(__half2*)&g_h1s[r0 * 64 + colx] = h0;
        if (r0 + 8 < n) *(__half2*)&g_h1s[(r0 + 8) * 64 + colx] = h1;
    }
}

// ---------------------------------------------------------------------------
// Fused scan + dinv + in-place h1s dinv scaling.
// ---------------------------------------------------------------------------
__global__ void k_scan(int n) {
    __shared__ int s_warp[8];
    __shared__ int s_base;
    __shared__ float s_dinv[SCAN_CHUNK];
    int t = threadIdx.x;
    int base = blockIdx.x * SCAN_CHUNK;
    int i0 = base + 2 * t;
    int a = (i0 < n) ? g_deg[i0] : 0;
    int c = (i0 + 1 < n) ? g_deg[i0 + 1] : 0;
    float da = rsqrtf((float)(a + 1));
    float dc = rsqrtf((float)(c + 1));
    s_dinv[2 * t] = da;
    s_dinv[2 * t + 1] = dc;
    if (i0 < n) g_dinv[i0] = da;
    if (i0 + 1 < n) g_dinv[i0 + 1] = dc;

    int sum2 = a + c;
    int lane = t & 31;
    int wid = t >> 5;
    int v = sum2;
#pragma unroll
    for (int o = 1; o < 32; o <<= 1) {
        int u = __shfl_up_sync(0xFFFFFFFFu, v, o);
        if (lane >= o) v += u;
    }
    if (lane == 31) s_warp[wid] = v;
    __syncthreads();
    if (t < 8) {
        int w = s_warp[t];
#pragma unroll
        for (int o = 1; o < 8; o <<= 1) {
            int u = __shfl_up_sync(0xFFu, w, o);
            if (t >= o) w += u;
        }
        s_warp[t] = w;
    }
    __syncthreads();
    int woff = wid ? s_warp[wid - 1] : 0;
    int incl = v + woff;
    if (t == 255) s_base = atomicAdd(&g_deg[NMAX], incl);
    __syncthreads();
    int excl = incl - sum2 + s_base;
    if (i0 < n) { g_rowstart[i0] = excl; g_cursor[i0] = excl; }
    if (i0 + 1 < n) { g_rowstart[i0 + 1] = excl + a; g_cursor[i0 + 1] = excl + a; }

    for (int i = t; i < 4096; i += 256) {
        int rl = i >> 3;
        int c8 = i & 7;
        int node = base + rl;
        if (node >= n) break;
        float s = s_dinv[rl];
        uint4 raw = *(const uint4*)&g_h1s[node * 64 + c8 * 8];
        __half2* hp = (__half2*)&raw;
        __half2 o[4];
#pragma unroll
        for (int p = 0; p < 4; p++) {
            float2 f = __half22float2(hp[p]);
            o[p] = f2h(f.x * s, f.y * s);
        }
        *(uint4*)&g_h1s[node * 64 + c8 * 8] = *(uint4*)o;
    }
}

// ---------------------------------------------------------------------------
// CSR fill: 4 edges per thread, independent atomics/stores (MLP=4).
// ---------------------------------------------------------------------------
__global__ void k_fill(const int* __restrict__ row, const int* __restrict__ col, int e) {
    int base = blockIdx.x * 1024 + threadIdx.x;
    int idx[4];
    int pos[4];
    int rv[4];
#pragma unroll
    for (int j = 0; j < 4; j++) {
        int i = base + j * 256;
        idx[j] = i;
        if (i < e) {
            int c = col[i];
            pos[j] = atomicAdd(&g_cursor[c], 1);
            rv[j] = row[i];
        }
    }
#pragma unroll
    for (int j = 0; j < 4; j++) {
        if (idx[j] < e) g_src[pos[j]] = rv[j];
    }
}

// ---------------------------------------------------------------------------
// Aggregation layer 1 (R11 shape: unroll x2 — empirically fastest).
// LDG.128 lane-group gather, fp16 HADD2 accumulate.
// grp=lane>>3 (4 rows/step), sub=lane&7 (16B chunk).
// ---------------------------------------------------------------------------
__global__ void k_agg1(int n) {
    int gw = (blockIdx.x * blockDim.x + threadIdx.x) >> 5;
    int lane = threadIdx.x & 31;
    if (gw >= n) return;

    int grp = lane >> 3;
    int sub = lane & 7;

    __half2 acc[4];
    if (grp == 0) {
        uint4 raw = *(const uint4*)&g_h1s[gw * 64 + sub * 8];
        __half2* hp = (__half2*)&raw;
        acc[0] = hp[0]; acc[1] = hp[1]; acc[2] = hp[2]; acc[3] = hp[3];
    } else {
        __half2 z = f2h(0.f, 0.f);
        acc[0] = z; acc[1] = z; acc[2] = z; acc[3] = z;
    }

    int start = g_rowstart[gw];
    int deg = g_deg[gw];

    for (int j0 = 0; j0 < deg; j0 += 32) {
        int cnt = min(32, deg - j0);
        int src = (lane < cnt) ? g_src[start + j0 + lane] : 0;
        int jj = 0;
        for (; jj + 8 <= cnt; jj += 8) {
            int sA = __shfl_sync(0xFFFFFFFFu, src, jj + grp);
            int sB = __shfl_sync(0xFFFFFFFFu, src, jj + 4 + grp);
            uint4 ra = *(const uint4*)&g_h1s[sA * 64 + sub * 8];
            uint4 rb = *(const uint4*)&g_h1s[sB * 64 + sub * 8];
            __half2* ha = (__half2*)&ra;
            __half2* hb = (__half2*)&rb;
            acc[0] = __hadd2(acc[0], ha[0]);
            acc[1] = __hadd2(acc[1], ha[1]);
            acc[2] = __hadd2(acc[2], ha[2]);
            acc[3] = __hadd2(acc[3], ha[3]);
            acc[0] = __hadd2(acc[0], hb[0]);
            acc[1] = __hadd2(acc[1], hb[1]);
            acc[2] = __hadd2(acc[2], hb[2]);
            acc[3] = __hadd2(acc[3], hb[3]);
        }
        for (; jj < cnt; jj += 4) {
            int sidx = jj + grp;
            int s = __shfl_sync(0xFFFFFFFFu, src, (sidx < cnt) ? sidx : 0);
            if (sidx < cnt) {
                uint4 raw = *(const uint4*)&g_h1s[s * 64 + sub * 8];
                __half2* hp = (__half2*)&raw;
                acc[0] = __hadd2(acc[0], hp[0]);
                acc[1] = __hadd2(acc[1], hp[1]);
                acc[2] = __hadd2(acc[2], hp[2]);
                acc[3] = __hadd2(acc[3], hp[3]);
            }
        }
    }

#pragma unroll
    for (int o = 8; o <= 16; o <<= 1) {
#pragma unroll
        for (int p = 0; p < 4; p++) {
            unsigned u = __shfl_xor_sync(0xFFFFFFFFu, *(unsigned*)&acc[p], o);
            acc[p] = __hadd2(acc[p], *(__half2*)&u);
        }
    }

    if (lane < 8) {
        *(uint4*)&g_agg1[gw * 64 + lane * 8] = *(uint4*)acc;
    }
}

// ---------------------------------------------------------------------------
// GEMM2 (tensor cores): a = relu(agg1*dinv + b1); h2s = fp16((a@W2)*dinv)
// 128-row tile, 8 warps x 16 rows, N=32 (2 B-tiles).
// ---------------------------------------------------------------------------
__global__ void __launch_bounds__(256) k_gemm2(const float* __restrict__ W2,
                                               const float* __restrict__ b1, int n) {
    __shared__ __align__(16) __half As[128][72];
    __shared__ __align__(16) __half Bs[64][72];

    int t = threadIdx.x;
    int rowbase = blockIdx.x * 128;

    // W2 [64][32] fp32 -> Bs fp16 (512 float4)
    const float4* W4 = (const float4*)W2;
    for (int i = t; i < 512; i += 256) {
        int k = i >> 3;
        int c4 = i & 7;
        float4 v = W4[i];
        __half2 p0 = f2h(v.x, v.y);
        __half2 p1 = f2h(v.z, v.w);
        uint2 u;
        u.x = *(uint32_t*)&p0;
        u.y = *(uint32_t*)&p1;
        *(uint2*)&Bs[k][c4 * 4] = u;
    }

    // As: relu(agg1*dinv + b1) in fp32, store fp16. 128 rows x 16 chunks of 4.
    const uint2* a2 = (const uint2*)g_agg1;
    const float4* b14 = (const float4*)b1;
    for (int i = t; i < 2048; i += 256) {
        int r = i >> 4;
        int c4 = i & 15;
        int gr = rowbase + r;
        float4 v = make_float4(0.f, 0.f, 0.f, 0.f);
        if (gr < n) {
            uint2 raw = a2[gr * 16 + c4];
            float2 u01 = __half22float2(*(__half2*)&raw.x);
            float2 u23 = __half22float2(*(__half2*)&raw.y);
            float s = g_dinv[gr];
            float4 bb = b14[c4];
            v.x = fmaxf(fmaf(u01.x, s, bb.x), 0.f);
            v.y = fmaxf(fmaf(u01.y, s, bb.y), 0.f);
            v.z = fmaxf(fmaf(u23.x, s, bb.z), 0.f);
            v.w = fmaxf(fmaf(u23.y, s, bb.w), 0.f);
        }
        __half2 p0 = f2h(v.x, v.y);
        __half2 p1 = f2h(v.z, v.w);
        uint2 u;
        u.x = *(uint32_t*)&p0;
        u.y = *(uint32_t*)&p1;
        *(uint2*)&As[r][c4 * 4] = u;
    }
    __syncthreads();

    int warp = t >> 5;
    int lane = t & 31;
    int m0 = warp * 16;

    float d[4][4];
#pragma unroll
    for (int nt = 0; nt < 4; nt++) {
        d[nt][0] = 0.f; d[nt][1] = 0.f; d[nt][2] = 0.f; d[nt][3] = 0.f;
    }

#pragma unroll
    for (int k0 = 0; k0 < 64; k0 += 16) {
        uint32_t afr[4];
        uint32_t aaddr = (uint32_t)__cvta_generic_to_shared(
            &As[m0 + (lane & 15)][k0 + (lane >> 4) * 8]);
        ldsm_a(afr, aaddr);
#pragma unroll
        for (int nn = 0; nn < 2; nn++) {
            uint32_t bfr[4];
            uint32_t baddr = (uint32_t)__cvta_generic_to_shared(
                &Bs[k0 + (lane & 15)][nn * 16 + (lane >> 4) * 8]);
            ldsm_bt(bfr, baddr);
            mma16816(d[nn * 2], afr, bfr[0], bfr[1]);
            mma16816(d[nn * 2 + 1], afr, bfr[2], bfr[3]);
        }
    }

    int r0 = rowbase + m0 + (lane >> 2);
    int cbase = (lane & 3) * 2;
    float s0 = (r0 < n) ? g_dinv[r0] : 0.f;
    float s1 = (r0 + 8 < n) ? g_dinv[r0 + 8] : 0.f;
#pragma unroll
    for (int nt = 0; nt < 4; nt++) {
        int colx = nt * 8 + cbase;
        __half2 h0 = f2h(d[nt][0] * s0, d[nt][1] * s0);
        __half2 h1 = f2h(d[nt][2] * s1, d[nt][3] * s1);
        if (r0 < n) *(__half2*)&g_h2s[r0 * 32 + colx] = h0;
        if (r0 + 8 < n) *(__half2*)&g_h2s[(r0 + 8) * 32 + colx] = h1;
    }
}

// ---------------------------------------------------------------------------
// Aggregation layer 2 + log_softmax. 64B rows: grp=lane>>2 (8 rows/step),
// sub=lane&3. Unrolled x2 (16 sources in flight).
// ---------------------------------------------------------------------------
__global__ void k_agg2_lsm(const float* __restrict__ b2, float* __restrict__ out, int n) {
    __shared__ __align__(16) __half s_red[8][32];

    int warp = threadIdx.x >> 5;
    int gw = (blockIdx.x * blockDim.x + threadIdx.x) >> 5;
    int lane = threadIdx.x & 31;
    if (gw >= n) return;

    int grp = lane >> 2;
    int sub = lane & 3;

    __half2 acc[4];
    if (grp == 0) {
        uint4 raw = *(const uint4*)&g_h2s[gw * 32 + sub * 8];
        __half2* hp = (__half2*)&raw;
        acc[0] = hp[0]; acc[1] = hp[1]; acc[2] = hp[2]; acc[3] = hp[3];
    } else {
        __half2 z = f2h(0.f, 0.f);
        acc[0] = z; acc[1] = z; acc[2] = z; acc[3] = z;
    }

    int start = g_rowstart[gw];
    int deg = g_deg[gw];

    for (int j0 = 0; j0 < deg; j0 += 32) {
        int cnt = min(32, deg - j0);
        int src = (lane < cnt) ? g_src[start + j0 + lane] : 0;
        int jj = 0;
        for (; jj + 16 <= cnt; jj += 16) {
            int sA = __shfl_sync(0xFFFFFFFFu, src, jj + grp);
            int sB = __shfl_sync(0xFFFFFFFFu, src, jj + 8 + grp);
            uint4 ra = *(const uint4*)&g_h2s[sA * 32 + sub * 8];
            uint4 rb = *(const uint4*)&g_h2s[sB * 32 + sub * 8];
            __half2* ha = (__half2*)&ra;
            __half2* hb = (__half2*)&rb;
#pragma unroll
            for (int p = 0; p < 4; p++) {
                acc[p] = __hadd2(acc[p], ha[p]);
                acc[p] = __hadd2(acc[p], hb[p]);
            }
        }
        for (; jj < cnt; jj += 8) {
            int sidx = jj + grp;
            int s = __shfl_sync(0xFFFFFFFFu, src, (sidx < cnt) ? sidx : 0);
            if (sidx < cnt) {
                uint4 raw = *(const uint4*)&g_h2s[s * 32 + sub * 8];
                __half2* hp = (__half2*)&raw;
#pragma unroll
                for (int p = 0; p < 4; p++) {
                    acc[p] = __hadd2(acc[p], hp[p]);
                }
            }
        }
    }

#pragma unroll
    for (int o = 4; o <= 16; o <<= 1) {
#pragma unroll
        for (int p = 0; p < 4; p++) {
            unsigned u = __shfl_xor_sync(0xFFFFFFFFu, *(unsigned*)&acc[p], o);
            acc[p] = __hadd2(acc[p], *(__half2*)&u);
        }
    }

    if (lane < 4) {
        *(uint4*)&s_red[warp][lane * 8] = *(uint4*)acc;
    }
    __syncwarp();

    float z = fmaf(__half2float(s_red[warp][lane]), g_dinv[gw], b2[lane]);
    float m = z;
#pragma unroll
    for (int o = 16; o; o >>= 1) m = fmaxf(m, __shfl_xor_sync(0xFFFFFFFFu, m, o));
    float ex = expf(z - m);
    float s = ex;
#pragma unroll
    for (int o = 16; o; o >>= 1) s += __shfl_xor_sync(0xFFFFFFFFu, s, o);
    out[gw * 32 + lane] = z - m - logf(s);
}

// ---------------------------------------------------------------------------
extern "C" void kernel_launch(void* const* d_in, const int* in_sizes, int n_in,
                              void* d_out, int out_size) {
    const float* x = (const float*)d_in[0];
    const int* ei = (const int*)d_in[1];
    const float* W1 = (const float*)d_in[2];
    const float* b1 = (const float*)d_in[3];
    const float* W2 = (const float*)d_in[4];
    const float* b2 = (const float*)d_in[5];
    float* out = (float*)d_out;

    int n = in_sizes[0] / 64;
    int e = in_sizes[1] / 2;
    const int* row = ei;
    const int* col = ei + e;

    void* degp = 0;
    cudaGetSymbolAddress(&degp, g_deg);
    cudaMemsetAsync(degp, 0, (NMAX + 1) * sizeof(int));

    int gemmBlocks = (n + 127) / 128;
    int cntBlocks = (e + CNT_EDGES_PER_BLOCK - 1) / CNT_EDGES_PER_BLOCK;
    k_gemm1_count<<<gemmBlocks + cntBlocks, 256>>>(x, W1, col, n, e, gemmBlocks);

    int nb = (n + SCAN_CHUNK - 1) / SCAN_CHUNK;
    k_scan<<<nb, 256>>>(n);
    k_fill<<<(e + 1023) / 1024, 256>>>(row, col, e);

    k_agg1<<<(n + 7) / 8, 256>>>(n);

    k_gemm2<<<(n + 127) / 128, 256>>>(W2, b1, n);
    k_agg2_lsm<<<(n + 7) / 8, 256>>>(b2, out, n);
}